// round 4
// baseline (speedup 1.0000x reference)
#include <cuda_runtime.h>

// Problem constants (fixed by setup_inputs)
#define NF 1000
#define NB 2049
#define EPSV 1.1920928955078125e-07f   // float32 eps
#define SQEPS 3.45266983e-04f          // sqrt(eps)

#define WARPS 8
#define KF 16    // f-values per thread in reduction kernels
#define STAGES 3
#define KF3 4    // f-values per thread in final kernel

// Accumulators / tables (no cudaMalloc allowed). Zero-initialized at load;
// k_norm1/k_norm2 re-zero them after consuming -> clean state per graph replay.
__device__ float4 g_acc1[NB * 4];   // per (b,s): {sum|y0|^2, sum|y1|^2, Re sum y0 y1*, Im sum y0 y1*}
__device__ float4 g_acc2[NB * 4];
__device__ float4 g_Rn1[NB * 4];    // normalized R, iteration 1
__device__ float4 g_Rn2[NB * 4];    // normalized R, iteration 2

// 16-byte async copy, predicated via src-size (0 => zero-fill, no gmem read)
__device__ __forceinline__ void cp16(float4* dst, const float4* src, int sz) {
    unsigned d = (unsigned)__cvta_generic_to_shared(dst);
    asm volatile("cp.async.cg.shared.global [%0], [%1], 16, %2;"
                 :: "r"(d), "l"(src), "r"(sz) : "memory");
}
#define CP_COMMIT() asm volatile("cp.async.commit_group;" ::: "memory")
#define CP_WAIT2()  asm volatile("cp.async.wait_group 2;" ::: "memory")
#define CP_WAIT0()  asm volatile("cp.async.wait_group 0;" ::: "memory")

// Block reduction over threadIdx.y (8 warps) + atomics into acc.
// red buffer is provided by caller (unioned with the cp.async staging smem).
__device__ __forceinline__ void block_reduce_atomic(
    const float a00[4], const float a11[4], const float are[4], const float aim[4],
    int b, bool bok, float4* acc, float (*red)[32][17])
{
    int lane = threadIdx.x, ty = threadIdx.y;
    float* p = red[ty][lane];
#pragma unroll
    for (int s = 0; s < 4; s++) {
        p[s]      = a00[s];
        p[4 + s]  = a11[s];
        p[8 + s]  = are[s];
        p[12 + s] = aim[s];
    }
    __syncthreads();
#pragma unroll
    for (int st = WARPS / 2; st >= 1; st >>= 1) {
        if (ty < st) {
            float* q = red[ty + st][lane];
#pragma unroll
            for (int i = 0; i < 16; i++) p[i] += q[i];
        }
        __syncthreads();
    }
    if (ty == 0 && bok) {
#pragma unroll
        for (int s = 0; s < 4; s++) {
            float* dst = ((float*)acc) + (b * 4 + s) * 4;
            atomicAdd(dst + 0, p[s]);
            atomicAdd(dst + 1, p[4 + s]);
            atomicAdd(dst + 2, p[8 + s]);
            atomicAdd(dst + 3, p[12 + s]);
        }
    }
}

// Issue the 4 y-component copies for pipeline step k into slot k%STAGES
#define ISSUE_Y(k)                                                              \
    { int f_ = fbase + (k) * WARPS;                                             \
      int p_ = (bok && f_ < NF) ? 16 : 0;                                       \
      int fc_ = (f_ < NF) ? f_ : 0;                                             \
      const float4* py_ = y + ((size_t)fc_ * NB + bc) * 4;                      \
      int st_ = (k) % STAGES;                                                   \
      cp16(&sy[st_][0][tid], py_ + 0, p_);                                      \
      cp16(&sy[st_][1][tid], py_ + 1, p_);                                      \
      cp16(&sy[st_][2][tid], py_ + 2, p_);                                      \
      cp16(&sy[st_][3][tid], py_ + 3, p_);                                      \
      CP_COMMIT(); }

// Pass 1: reduction over original y (forward f order), cp.async pipelined.
__global__ void __launch_bounds__(256, 4) k_red1(const float4* __restrict__ y)
{
    __shared__ float4 sy[STAGES][4][256];  // 48 KB, reused as reduction buffer
    int lane = threadIdx.x, ty = threadIdx.y;
    int tid = ty * 32 + lane;
    int b = blockIdx.x * 32 + lane;
    bool bok = b < NB;
    int bc = bok ? b : 0;
    int fbase = blockIdx.y * (WARPS * KF) + ty;

    float a00[4] = {0,0,0,0}, a11[4] = {0,0,0,0}, are[4] = {0,0,0,0}, aim[4] = {0,0,0,0};

    ISSUE_Y(0);
    ISSUE_Y(1);
#pragma unroll
    for (int k = 0; k < KF; k++) {
        ISSUE_Y(k + 2);
        CP_WAIT2();
        int st = k % STAGES;
        float4 q0 = sy[st][0][tid], q1 = sy[st][1][tid];
        float4 q2 = sy[st][2][tid], q3 = sy[st][3][tid];
#define ACC_S(i, c0r, c0i, c1r, c1i)          \
        a00[i] += c0r*c0r + c0i*c0i;          \
        a11[i] += c1r*c1r + c1i*c1i;          \
        are[i] += c0r*c1r + c0i*c1i;          \
        aim[i] += c0i*c1r - c0r*c1i;
        ACC_S(0, q0.x, q1.x, q2.x, q3.x)
        ACC_S(1, q0.y, q1.y, q2.y, q3.y)
        ACC_S(2, q0.z, q1.z, q2.z, q3.z)
        ACC_S(3, q0.w, q1.w, q2.w, q3.w)
#undef ACC_S
    }
    CP_WAIT0();
    __syncthreads();   // staging smem now idle for ALL threads -> safe to reuse
    block_reduce_atomic(a00, a11, are, aim, b, bok, g_acc1,
                        reinterpret_cast<float(*)[32][17]>(sy));
}

__global__ void k_norm1() {
    int i = blockIdx.x * 256 + threadIdx.x;
    if (i >= NB * 4) return;
    float4 a = g_acc1[i];
    float inv = 1.0f / (EPSV + 0.5f * (a.x + a.y));
    g_Rn1[i] = make_float4(a.x * inv, a.y * inv, a.z * inv, a.w * inv);
    g_acc1[i] = make_float4(0.f, 0.f, 0.f, 0.f);   // reset for next replay
}

// Pass 2: apply iteration-1 filter, reduce iteration-2 stats, write v_out.
// Reversed f order for L2 tail retention from pass 1. cp.async pipelined.
__global__ void __launch_bounds__(256, 4) k_iter(const float4* __restrict__ y,
                                                 const float4* __restrict__ x,
                                                 float4* __restrict__ vout)
{
    __shared__ float4 sy[STAGES][4][256];  // 48 KB, reused as reduction buffer
    int lane = threadIdx.x, ty = threadIdx.y;
    int tid = ty * 32 + lane;
    int b = blockIdx.x * 32 + lane;
    bool bok = b < NB;
    int bc = bok ? b : 0;
    int byr = gridDim.y - 1 - blockIdx.y;
    int fbase = byr * (WARPS * KF) + ty;

    float a00[4] = {0,0,0,0}, a11[4] = {0,0,0,0}, are[4] = {0,0,0,0}, aim[4] = {0,0,0,0};

    float4 Rn[4];
#pragma unroll
    for (int s = 0; s < 4; s++) Rn[s] = g_Rn1[bc * 4 + s];

    // x register prefetch, 2-deep
    float4 xb[2];
    {
        int f0c = (fbase < NF) ? fbase : 0;
        int f1 = fbase + WARPS;
        int f1c = (f1 < NF) ? f1 : 0;
        xb[0] = __ldg(x + (size_t)f0c * NB + bc);
        xb[1] = __ldg(x + (size_t)f1c * NB + bc);
    }

    ISSUE_Y(0);
    ISSUE_Y(1);
#pragma unroll
    for (int k = 0; k < KF; k++) {
        ISSUE_Y(k + 2);
        float4 xv = xb[k & 1];
        {   // prefetch x for step k+2
            int f2 = fbase + (k + 2) * WARPS;
            int f2c = (f2 < NF) ? f2 : 0;
            xb[k & 1] = __ldg(x + (size_t)f2c * NB + bc);
        }
        CP_WAIT2();
        int st = k % STAGES;
        float4 q0 = sy[st][0][tid], q1 = sy[st][1][tid];
        float4 q2 = sy[st][2][tid], q3 = sy[st][3][tid];

        float i0r[4] = {q0.x, q0.y, q0.z, q0.w};
        float i0i[4] = {q1.x, q1.y, q1.z, q1.w};
        float i1r[4] = {q2.x, q2.y, q2.z, q2.w};
        float i1i[4] = {q3.x, q3.y, q3.z, q3.w};

        float v[4];
        float c00 = SQEPS, c11 = SQEPS, cre = 0.f, cim = 0.f;
#pragma unroll
        for (int s = 0; s < 4; s++) {
            v[s] = 0.5f * (i0r[s]*i0r[s] + i0i[s]*i0i[s] + i1r[s]*i1r[s] + i1i[s]*i1i[s]);
            c00 += v[s] * Rn[s].x;
            c11 += v[s] * Rn[s].y;
            cre += v[s] * Rn[s].z;
            cim += v[s] * Rn[s].w;
        }
        float det = c00 * c11 - (cre * cre + cim * cim);
        float id = 1.0f / det;
        float w0r = id * (c11 * xv.x - (cre * xv.z - cim * xv.w));
        float w0i = id * (c11 * xv.y - (cre * xv.w + cim * xv.z));
        float w1r = id * (c00 * xv.z - (cre * xv.x + cim * xv.y));
        float w1i = id * (c00 * xv.w - (cre * xv.y - cim * xv.x));

        float v2[4];
#pragma unroll
        for (int s = 0; s < 4; s++) {
            float o0r = v[s] * (Rn[s].x * w0r + Rn[s].z * w1r - Rn[s].w * w1i);
            float o0i = v[s] * (Rn[s].x * w0i + Rn[s].z * w1i + Rn[s].w * w1r);
            float o1r = v[s] * (Rn[s].z * w0r + Rn[s].w * w0i + Rn[s].y * w1r);
            float o1i = v[s] * (Rn[s].z * w0i - Rn[s].w * w0r + Rn[s].y * w1i);
            float t00 = o0r*o0r + o0i*o0i;
            float t11 = o1r*o1r + o1i*o1i;
            a00[s] += t00;
            a11[s] += t11;
            are[s] += o0r*o1r + o0i*o1i;
            aim[s] += o0i*o1r - o0r*o1i;
            v2[s] = 0.5f * (t00 + t11);
        }
        int f = fbase + k * WARPS;
        if (bok && f < NF)
            __stcs(vout + (size_t)f * NB + b, make_float4(v2[0], v2[1], v2[2], v2[3]));
    }
    CP_WAIT0();
    __syncthreads();
    block_reduce_atomic(a00, a11, are, aim, b, bok, g_acc2,
                        reinterpret_cast<float(*)[32][17]>(sy));
}

// Normalize iteration-2 R, emit R_out (B, C, C, 2, S), reset acc2.
__global__ void k_norm2(float* __restrict__ rout) {
    int i = blockIdx.x * 256 + threadIdx.x;
    if (i >= NB * 4) return;
    float4 a = g_acc2[i];
    float inv = 1.0f / (EPSV + 0.5f * (a.x + a.y));
    float r00 = a.x * inv, r11 = a.y * inv, zr = a.z * inv, zi = a.w * inv;
    g_Rn2[i] = make_float4(r00, r11, zr, zi);
    g_acc2[i] = make_float4(0.f, 0.f, 0.f, 0.f);   // reset for next replay
    int b = i >> 2, s = i & 3;
    float* p = rout + b * 32 + s;   // (((b*2+c)*2+d)*2+r)*4+s
    p[0]  = r00;  p[4]  = 0.f;      // R[0,0]
    p[8]  = zr;   p[12] = zi;       // R[0,1]
    p[16] = zr;   p[20] = -zi;      // R[1,0] = conj
    p[24] = r11;  p[28] = 0.f;      // R[1,1]
}

// Pass 3: read v2 (written by pass 2) + x, build the iteration-2 Wiener filter,
// write y_out. No y re-read, no yc1 recompute.
__global__ void __launch_bounds__(256) k_final(const float4* __restrict__ vin,
                                               const float4* __restrict__ x,
                                               float4* __restrict__ yout)
{
    int lane = threadIdx.x;
    int b = blockIdx.x * 32 + lane;
    if (b >= NB) return;

    float4 Rn[4];
#pragma unroll
    for (int s = 0; s < 4; s++) Rn[s] = g_Rn2[b * 4 + s];

    int f0 = blockIdx.y * (WARPS * KF3) + threadIdx.y;
#pragma unroll
    for (int k = 0; k < KF3; k++) {
        int f = f0 + k * WARPS;
        if (f >= NF) continue;
        size_t p = (size_t)f * NB + b;
        float4 vv = __ldcs(vin + p);
        float4 xv = x[p];
        float va[4] = {vv.x, vv.y, vv.z, vv.w};

        float c00 = SQEPS, c11 = SQEPS, cre = 0.f, cim = 0.f;
#pragma unroll
        for (int s = 0; s < 4; s++) {
            c00 += va[s] * Rn[s].x;
            c11 += va[s] * Rn[s].y;
            cre += va[s] * Rn[s].z;
            cim += va[s] * Rn[s].w;
        }
        float det = c00 * c11 - (cre * cre + cim * cim);
        float id = 1.0f / det;
        float w0r = id * (c11 * xv.x - (cre * xv.z - cim * xv.w));
        float w0i = id * (c11 * xv.y - (cre * xv.w + cim * xv.z));
        float w1r = id * (c00 * xv.z - (cre * xv.x + cim * xv.y));
        float w1i = id * (c00 * xv.w - (cre * xv.y - cim * xv.x));

        float o0r[4], o0i[4], o1r[4], o1i[4];
#pragma unroll
        for (int s = 0; s < 4; s++) {
            o0r[s] = va[s] * (Rn[s].x * w0r + Rn[s].z * w1r - Rn[s].w * w1i);
            o0i[s] = va[s] * (Rn[s].x * w0i + Rn[s].z * w1i + Rn[s].w * w1r);
            o1r[s] = va[s] * (Rn[s].z * w0r + Rn[s].w * w0i + Rn[s].y * w1r);
            o1i[s] = va[s] * (Rn[s].z * w0i - Rn[s].w * w0r + Rn[s].y * w1i);
        }

        float4* po = yout + p * 4;
        __stcs(po + 0, make_float4(o0r[0], o0r[1], o0r[2], o0r[3]));
        __stcs(po + 1, make_float4(o0i[0], o0i[1], o0i[2], o0i[3]));
        __stcs(po + 2, make_float4(o1r[0], o1r[1], o1r[2], o1r[3]));
        __stcs(po + 3, make_float4(o1i[0], o1i[1], o1i[2], o1i[3]));
    }
}

extern "C" void kernel_launch(void* const* d_in, const int* in_sizes, int n_in,
                              void* d_out, int out_size)
{
    const float4* y = (const float4*)d_in[0];
    const float4* x = (const float4*)d_in[1];
    float* out = (float*)d_out;

    float4* yout = (float4*)out;                                     // (F,B,C,2,S)
    float4* vout = (float4*)(out + (size_t)NF * NB * 16);            // (F,B,S)
    float*  rout = out + (size_t)NF * NB * 16 + (size_t)NF * NB * 4; // (B,C,C,2,S)

    dim3 blk(32, WARPS);
    dim3 grd((NB + 31) / 32, (NF + WARPS * KF - 1) / (WARPS * KF));
    dim3 grd3((NB + 31) / 32, (NF + WARPS * KF3 - 1) / (WARPS * KF3));
    int nblk_small = (NB * 4 + 255) / 256;

    k_red1<<<grd, blk>>>(y);
    k_norm1<<<nblk_small, 256>>>();
    k_iter<<<grd, blk>>>(y, x, vout);
    k_norm2<<<nblk_small, 256>>>(rout);
    k_final<<<grd3, blk>>>(vout, x, yout);
}

// round 5
// speedup vs baseline: 1.2271x; 1.2271x over previous
#include <cuda_runtime.h>

// Problem constants (fixed by setup_inputs)
#define NF 1000
#define NB 2049
#define EPSV 1.1920928955078125e-07f   // float32 eps
#define SQEPS 3.45266983e-04f          // sqrt(eps)

#define WARPS 8
#define KF 8    // f-values per thread in reduction kernels
#define KF3 4   // f-values per thread in final kernel

// Accumulators (no cudaMalloc allowed). Zero-initialized at module load.
// Reset protocol (stream-ordered, valid across graph replays):
//   g_acc1: accumulated by k_red1, read by k_iter, RESET by k_final.
//   g_acc2: RESET by k_red1, accumulated by k_iter, read by k_final.
__device__ float4 g_acc1[NB * 4];   // per (b,s): {sum|y0|^2, sum|y1|^2, Re sum y0 y1*, Im sum y0 y1*}
__device__ float4 g_acc2[NB * 4];

// Normalize one accumulator entry -> Rn {r00, r11, Re r01, Im r01}
__device__ __forceinline__ float4 norm_acc(float4 a) {
    float inv = 1.0f / (EPSV + 0.5f * (a.x + a.y));
    return make_float4(a.x * inv, a.y * inv, a.z * inv, a.w * inv);
}

// Block reduction over threadIdx.y (8 warps) + atomics into acc.
__device__ __forceinline__ void block_reduce_atomic(
    const float a00[4], const float a11[4], const float are[4], const float aim[4],
    int b, bool bok, float4* acc)
{
    __shared__ float red[WARPS][32][17];
    int lane = threadIdx.x, ty = threadIdx.y;
    float* p = red[ty][lane];
#pragma unroll
    for (int s = 0; s < 4; s++) {
        p[s]      = a00[s];
        p[4 + s]  = a11[s];
        p[8 + s]  = are[s];
        p[12 + s] = aim[s];
    }
    __syncthreads();
#pragma unroll
    for (int st = WARPS / 2; st >= 1; st >>= 1) {
        if (ty < st) {
            float* q = red[ty + st][lane];
#pragma unroll
            for (int i = 0; i < 16; i++) p[i] += q[i];
        }
        __syncthreads();
    }
    if (ty == 0 && bok) {
#pragma unroll
        for (int s = 0; s < 4; s++) {
            float* dst = ((float*)acc) + (b * 4 + s) * 4;
            atomicAdd(dst + 0, p[s]);
            atomicAdd(dst + 1, p[4 + s]);
            atomicAdd(dst + 2, p[8 + s]);
            atomicAdd(dst + 3, p[12 + s]);
        }
    }
}

// Pass 1: reduction over original y (forward f order). Also resets g_acc2
// for this replay (k_iter accumulates it strictly after this kernel).
__global__ void __launch_bounds__(256, 5) k_red1(const float4* __restrict__ y)
{
    int lane = threadIdx.x, ty = threadIdx.y;
    int tid = ty * 32 + lane;
    if (blockIdx.y == 0 && tid < 128) {
        int idx = blockIdx.x * 128 + tid;
        if (idx < NB * 4) g_acc2[idx] = make_float4(0.f, 0.f, 0.f, 0.f);
    }

    int b = blockIdx.x * 32 + lane;
    bool bok = b < NB;
    int f0 = blockIdx.y * (WARPS * KF) + ty;

    float a00[4] = {0,0,0,0}, a11[4] = {0,0,0,0}, are[4] = {0,0,0,0}, aim[4] = {0,0,0,0};
    if (bok) {
#pragma unroll
        for (int k = 0; k < KF; k++) {
            int f = f0 + k * WARPS;
            if (f < NF) {
                const float4* py = y + (size_t)(f * NB + b) * 4;
                float4 q0 = py[0], q1 = py[1], q2 = py[2], q3 = py[3];
#define ACC_S(i, c0r, c0i, c1r, c1i)                  \
                a00[i] += c0r*c0r + c0i*c0i;          \
                a11[i] += c1r*c1r + c1i*c1i;          \
                are[i] += c0r*c1r + c0i*c1i;          \
                aim[i] += c0i*c1r - c0r*c1i;
                ACC_S(0, q0.x, q1.x, q2.x, q3.x)
                ACC_S(1, q0.y, q1.y, q2.y, q3.y)
                ACC_S(2, q0.z, q1.z, q2.z, q3.z)
                ACC_S(3, q0.w, q1.w, q2.w, q3.w)
#undef ACC_S
            }
        }
    }
    block_reduce_atomic(a00, a11, are, aim, b, bok, g_acc1);
}

// Pass 2: apply iteration-1 filter (Rn1 computed inline from g_acc1), reduce
// iteration-2 stats into g_acc2, write v_out. Reversed f order for L2 reuse.
__global__ void __launch_bounds__(256, 5) k_iter(const float4* __restrict__ y,
                                                 const float4* __restrict__ x,
                                                 float4* __restrict__ vout)
{
    int lane = threadIdx.x, ty = threadIdx.y;
    int b = blockIdx.x * 32 + lane;
    bool bok = b < NB;
    int bc = bok ? b : 0;
    int byr = gridDim.y - 1 - blockIdx.y;
    int f0 = byr * (WARPS * KF) + ty;

    float a00[4] = {0,0,0,0}, a11[4] = {0,0,0,0}, are[4] = {0,0,0,0}, aim[4] = {0,0,0,0};
    if (bok) {
        float4 Rn[4];
#pragma unroll
        for (int s = 0; s < 4; s++) Rn[s] = norm_acc(g_acc1[bc * 4 + s]);
#pragma unroll
        for (int k = 0; k < KF; k++) {
            int f = f0 + k * WARPS;
            if (f < NF) {
                const float4* py = y + (size_t)(f * NB + b) * 4;
                float4 q0 = py[0], q1 = py[1], q2 = py[2], q3 = py[3];
                float4 xv = x[(size_t)(f * NB + b)];
                float i0r[4] = {q0.x, q0.y, q0.z, q0.w};
                float i0i[4] = {q1.x, q1.y, q1.z, q1.w};
                float i1r[4] = {q2.x, q2.y, q2.z, q2.w};
                float i1i[4] = {q3.x, q3.y, q3.z, q3.w};

                float v[4];
                float c00 = SQEPS, c11 = SQEPS, cre = 0.f, cim = 0.f;
#pragma unroll
                for (int s = 0; s < 4; s++) {
                    v[s] = 0.5f * (i0r[s]*i0r[s] + i0i[s]*i0i[s] + i1r[s]*i1r[s] + i1i[s]*i1i[s]);
                    c00 += v[s] * Rn[s].x;
                    c11 += v[s] * Rn[s].y;
                    cre += v[s] * Rn[s].z;
                    cim += v[s] * Rn[s].w;
                }
                float det = c00 * c11 - (cre * cre + cim * cim);
                float id = 1.0f / det;
                float w0r = id * (c11 * xv.x - (cre * xv.z - cim * xv.w));
                float w0i = id * (c11 * xv.y - (cre * xv.w + cim * xv.z));
                float w1r = id * (c00 * xv.z - (cre * xv.x + cim * xv.y));
                float w1i = id * (c00 * xv.w - (cre * xv.y - cim * xv.x));

                float v2[4];
#pragma unroll
                for (int s = 0; s < 4; s++) {
                    float o0r = v[s] * (Rn[s].x * w0r + Rn[s].z * w1r - Rn[s].w * w1i);
                    float o0i = v[s] * (Rn[s].x * w0i + Rn[s].z * w1i + Rn[s].w * w1r);
                    float o1r = v[s] * (Rn[s].z * w0r + Rn[s].w * w0i + Rn[s].y * w1r);
                    float o1i = v[s] * (Rn[s].z * w0i - Rn[s].w * w0r + Rn[s].y * w1i);
                    float t00 = o0r*o0r + o0i*o0i;
                    float t11 = o1r*o1r + o1i*o1i;
                    a00[s] += t00;
                    a11[s] += t11;
                    are[s] += o0r*o1r + o0i*o1i;
                    aim[s] += o0i*o1r - o0r*o1i;
                    v2[s] = 0.5f * (t00 + t11);
                }
                __stcs(vout + (size_t)(f * NB + b),
                       make_float4(v2[0], v2[1], v2[2], v2[3]));
            }
        }
    }
    block_reduce_atomic(a00, a11, are, aim, b, bok, g_acc2);
}

// Pass 3: read v2 + x, build the iteration-2 Wiener filter (Rn2 inline from
// g_acc2), write y_out. blockIdx.y==0 additionally writes R_out and resets g_acc1.
__global__ void __launch_bounds__(256) k_final(const float4* __restrict__ vin,
                                               const float4* __restrict__ x,
                                               float4* __restrict__ yout,
                                               float* __restrict__ rout)
{
    int lane = threadIdx.x, ty = threadIdx.y;
    int tid = ty * 32 + lane;

    if (blockIdx.y == 0 && tid < 128) {    // reset acc1 (consumed by k_iter already)
        int idx = blockIdx.x * 128 + tid;
        if (idx < NB * 4) g_acc1[idx] = make_float4(0.f, 0.f, 0.f, 0.f);
    }

    int b = blockIdx.x * 32 + lane;
    if (b >= NB) return;

    float4 Rn[4];
#pragma unroll
    for (int s = 0; s < 4; s++) Rn[s] = norm_acc(g_acc2[b * 4 + s]);

    if (blockIdx.y == 0 && ty == 0) {      // emit R_out (B, C, C, 2, S)
#pragma unroll
        for (int s = 0; s < 4; s++) {
            float* p = rout + b * 32 + s;  // (((b*2+c)*2+d)*2+r)*4+s
            p[0]  = Rn[s].x;  p[4]  = 0.f;        // R[0,0]
            p[8]  = Rn[s].z;  p[12] = Rn[s].w;    // R[0,1]
            p[16] = Rn[s].z;  p[20] = -Rn[s].w;   // R[1,0] = conj
            p[24] = Rn[s].y;  p[28] = 0.f;        // R[1,1]
        }
    }

    int f0 = blockIdx.y * (WARPS * KF3) + ty;
#pragma unroll
    for (int k = 0; k < KF3; k++) {
        int f = f0 + k * WARPS;
        if (f >= NF) continue;
        size_t p = (size_t)f * NB + b;
        float4 vv = __ldcs(vin + p);
        float4 xv = x[p];
        float va[4] = {vv.x, vv.y, vv.z, vv.w};

        float c00 = SQEPS, c11 = SQEPS, cre = 0.f, cim = 0.f;
#pragma unroll
        for (int s = 0; s < 4; s++) {
            c00 += va[s] * Rn[s].x;
            c11 += va[s] * Rn[s].y;
            cre += va[s] * Rn[s].z;
            cim += va[s] * Rn[s].w;
        }
        float det = c00 * c11 - (cre * cre + cim * cim);
        float id = 1.0f / det;
        float w0r = id * (c11 * xv.x - (cre * xv.z - cim * xv.w));
        float w0i = id * (c11 * xv.y - (cre * xv.w + cim * xv.z));
        float w1r = id * (c00 * xv.z - (cre * xv.x + cim * xv.y));
        float w1i = id * (c00 * xv.w - (cre * xv.y - cim * xv.x));

        float o0r[4], o0i[4], o1r[4], o1i[4];
#pragma unroll
        for (int s = 0; s < 4; s++) {
            o0r[s] = va[s] * (Rn[s].x * w0r + Rn[s].z * w1r - Rn[s].w * w1i);
            o0i[s] = va[s] * (Rn[s].x * w0i + Rn[s].z * w1i + Rn[s].w * w1r);
            o1r[s] = va[s] * (Rn[s].z * w0r + Rn[s].w * w0i + Rn[s].y * w1r);
            o1i[s] = va[s] * (Rn[s].z * w0i - Rn[s].w * w0r + Rn[s].y * w1i);
        }

        float4* po = yout + p * 4;
        __stcs(po + 0, make_float4(o0r[0], o0r[1], o0r[2], o0r[3]));
        __stcs(po + 1, make_float4(o0i[0], o0i[1], o0i[2], o0i[3]));
        __stcs(po + 2, make_float4(o1r[0], o1r[1], o1r[2], o1r[3]));
        __stcs(po + 3, make_float4(o1i[0], o1i[1], o1i[2], o1i[3]));
    }
}

extern "C" void kernel_launch(void* const* d_in, const int* in_sizes, int n_in,
                              void* d_out, int out_size)
{
    const float4* y = (const float4*)d_in[0];
    const float4* x = (const float4*)d_in[1];
    float* out = (float*)d_out;

    float4* yout = (float4*)out;                                     // (F,B,C,2,S)
    float4* vout = (float4*)(out + (size_t)NF * NB * 16);            // (F,B,S)
    float*  rout = out + (size_t)NF * NB * 16 + (size_t)NF * NB * 4; // (B,C,C,2,S)

    dim3 blk(32, WARPS);
    dim3 grd((NB + 31) / 32, (NF + WARPS * KF - 1) / (WARPS * KF));
    dim3 grd3((NB + 31) / 32, (NF + WARPS * KF3 - 1) / (WARPS * KF3));

    k_red1<<<grd, blk>>>(y);
    k_iter<<<grd, blk>>>(y, x, vout);
    k_final<<<grd3, blk>>>(vout, x, yout, rout);
}

// round 6
// speedup vs baseline: 1.3429x; 1.0943x over previous
#include <cuda_runtime.h>

// Problem constants (fixed by setup_inputs)
#define NF 1000
#define NB 2049
#define EPSV 1.1920928955078125e-07f   // float32 eps
#define SQEPS 3.45266983e-04f          // sqrt(eps)

#define WARPS 8
#define KF 14                  // f-values per thread per phase
#define FPT (WARPS * KF)       // 112 f per tile
#define NBX 65                 // ceil(2049/32)
#define NTY 9                  // ceil(1000/112)
#define NBLK (NBX * NTY)       // 585 blocks; <= 592 resident @ 4 blocks/SM

// Accumulators (no cudaMalloc allowed). Zero-initialized at module load.
// g_acc2 reset at kernel start (before use in phase B of same run);
// g_acc1 reset in phase C (after its last read in phase B).
__device__ float4 g_acc1[NB * 4];   // per (b,s): {sum|y0|^2, sum|y1|^2, Re sum y0y1*, Im sum y0y1*}
__device__ float4 g_acc2[NB * 4];

// Grid-barrier state; self-resetting (last block out zeroes everything).
__device__ unsigned g_cnt1 = 0, g_cnt2 = 0, g_done = 0;

__device__ __forceinline__ void grid_barrier(unsigned* cnt) {
    __syncthreads();
    __threadfence();
    if (threadIdx.x == 0 && threadIdx.y == 0) {
        atomicAdd(cnt, 1u);
        while (atomicAdd(cnt, 0u) < (unsigned)NBLK) { }
    }
    __syncthreads();
    __threadfence();
}

// Normalize one accumulator entry -> Rn {r00, r11, Re r01, Im r01}
__device__ __forceinline__ float4 norm_acc(float4 a) {
    float inv = 1.0f / (EPSV + 0.5f * (a.x + a.y));
    return make_float4(a.x * inv, a.y * inv, a.z * inv, a.w * inv);
}

// Block reduction over threadIdx.y (8 warps) + atomics into acc.
__device__ __forceinline__ void block_reduce_atomic(
    const float a00[4], const float a11[4], const float are[4], const float aim[4],
    int b, bool bok, float4* acc, float (*red)[32][17])
{
    int lane = threadIdx.x, ty = threadIdx.y;
    float* p = red[ty][lane];
#pragma unroll
    for (int s = 0; s < 4; s++) {
        p[s]      = a00[s];
        p[4 + s]  = a11[s];
        p[8 + s]  = are[s];
        p[12 + s] = aim[s];
    }
    __syncthreads();
#pragma unroll
    for (int st = WARPS / 2; st >= 1; st >>= 1) {
        if (ty < st) {
            float* q = red[ty + st][lane];
#pragma unroll
            for (int i = 0; i < 16; i++) p[i] += q[i];
        }
        __syncthreads();
    }
    if (ty == 0 && bok) {
#pragma unroll
        for (int s = 0; s < 4; s++) {
            float* dst = ((float*)acc) + (b * 4 + s) * 4;
            atomicAdd(dst + 0, p[s]);
            atomicAdd(dst + 1, p[4 + s]);
            atomicAdd(dst + 2, p[8 + s]);
            atomicAdd(dst + 3, p[12 + s]);
        }
    }
    __syncthreads();   // smem reused by later phase
}

__global__ void __launch_bounds__(256, 4) k_fused(
    const float4* __restrict__ y,
    const float4* __restrict__ x,
    float4* __restrict__ vout,
    float4* __restrict__ yout,
    float* __restrict__ rout)
{
    __shared__ float red[WARPS][32][17];
    int lane = threadIdx.x, ty = threadIdx.y;
    int tid = ty * 32 + lane;
    int b = blockIdx.x * 32 + lane;
    bool bok = b < NB;
    int bc = bok ? b : 0;
    int f0 = blockIdx.y * FPT + ty;

    // Reset g_acc2 for this run (accumulated in phase B, after barrier 1)
    if (blockIdx.y == 0 && tid < 128) {
        int idx = blockIdx.x * 128 + tid;
        if (idx < NB * 4) g_acc2[idx] = make_float4(0.f, 0.f, 0.f, 0.f);
    }

    // ================= Phase A: reduce |y|^2 / y y^H over f =================
    {
        float a00[4] = {0,0,0,0}, a11[4] = {0,0,0,0}, are[4] = {0,0,0,0}, aim[4] = {0,0,0,0};
        if (bok) {
#pragma unroll
            for (int k = 0; k < KF; k++) {
                int f = f0 + k * WARPS;
                if (f < NF) {
                    const float4* py = y + (size_t)(f * NB + b) * 4;
                    float4 q0 = py[0], q1 = py[1], q2 = py[2], q3 = py[3];
#define ACC_S(i, c0r, c0i, c1r, c1i)                  \
                    a00[i] += c0r*c0r + c0i*c0i;      \
                    a11[i] += c1r*c1r + c1i*c1i;      \
                    are[i] += c0r*c1r + c0i*c1i;      \
                    aim[i] += c0i*c1r - c0r*c1i;
                    ACC_S(0, q0.x, q1.x, q2.x, q3.x)
                    ACC_S(1, q0.y, q1.y, q2.y, q3.y)
                    ACC_S(2, q0.z, q1.z, q2.z, q3.z)
                    ACC_S(3, q0.w, q1.w, q2.w, q3.w)
#undef ACC_S
                }
            }
        }
        block_reduce_atomic(a00, a11, are, aim, b, bok, g_acc1, red);
    }
    grid_barrier(&g_cnt1);

    // ====== Phase B: apply iter-1 filter (y tile now L2-hot), acc2, vout ======
    {
        float a00[4] = {0,0,0,0}, a11[4] = {0,0,0,0}, are[4] = {0,0,0,0}, aim[4] = {0,0,0,0};
        if (bok) {
            float4 Rn[4];
#pragma unroll
            for (int s = 0; s < 4; s++) Rn[s] = norm_acc(g_acc1[bc * 4 + s]);
#pragma unroll
            for (int k = KF - 1; k >= 0; k--) {     // reversed: hit freshest L2 lines first
                int f = f0 + k * WARPS;
                if (f < NF) {
                    const float4* py = y + (size_t)(f * NB + b) * 4;
                    float4 q0 = py[0], q1 = py[1], q2 = py[2], q3 = py[3];
                    float4 xv = x[(size_t)(f * NB + b)];
                    float i0r[4] = {q0.x, q0.y, q0.z, q0.w};
                    float i0i[4] = {q1.x, q1.y, q1.z, q1.w};
                    float i1r[4] = {q2.x, q2.y, q2.z, q2.w};
                    float i1i[4] = {q3.x, q3.y, q3.z, q3.w};

                    float v[4];
                    float c00 = SQEPS, c11 = SQEPS, cre = 0.f, cim = 0.f;
#pragma unroll
                    for (int s = 0; s < 4; s++) {
                        v[s] = 0.5f * (i0r[s]*i0r[s] + i0i[s]*i0i[s] + i1r[s]*i1r[s] + i1i[s]*i1i[s]);
                        c00 += v[s] * Rn[s].x;
                        c11 += v[s] * Rn[s].y;
                        cre += v[s] * Rn[s].z;
                        cim += v[s] * Rn[s].w;
                    }
                    float det = c00 * c11 - (cre * cre + cim * cim);
                    float id = 1.0f / det;
                    float w0r = id * (c11 * xv.x - (cre * xv.z - cim * xv.w));
                    float w0i = id * (c11 * xv.y - (cre * xv.w + cim * xv.z));
                    float w1r = id * (c00 * xv.z - (cre * xv.x + cim * xv.y));
                    float w1i = id * (c00 * xv.w - (cre * xv.y - cim * xv.x));

                    float v2[4];
#pragma unroll
                    for (int s = 0; s < 4; s++) {
                        float o0r = v[s] * (Rn[s].x * w0r + Rn[s].z * w1r - Rn[s].w * w1i);
                        float o0i = v[s] * (Rn[s].x * w0i + Rn[s].z * w1i + Rn[s].w * w1r);
                        float o1r = v[s] * (Rn[s].z * w0r + Rn[s].w * w0i + Rn[s].y * w1r);
                        float o1i = v[s] * (Rn[s].z * w0i - Rn[s].w * w0r + Rn[s].y * w1i);
                        float t00 = o0r*o0r + o0i*o0i;
                        float t11 = o1r*o1r + o1i*o1i;
                        a00[s] += t00;
                        a11[s] += t11;
                        are[s] += o0r*o1r + o0i*o1i;
                        aim[s] += o0i*o1r - o0r*o1i;
                        v2[s] = 0.5f * (t00 + t11);
                    }
                    // regular store -> stays in L2 for phase C (same block re-reads it)
                    vout[(size_t)f * NB + b] = make_float4(v2[0], v2[1], v2[2], v2[3]);
                }
            }
        }
        block_reduce_atomic(a00, a11, are, aim, b, bok, g_acc2, red);
    }
    grid_barrier(&g_cnt2);

    // ====== Phase C: iter-2 filter from (vout, x) [L2-hot], write y_out ======
    if (bok) {
        float4 Rn[4];
#pragma unroll
        for (int s = 0; s < 4; s++) Rn[s] = norm_acc(g_acc2[b * 4 + s]);

        if (blockIdx.y == 0 && ty == 0) {      // emit R_out (B, C, C, 2, S)
#pragma unroll
            for (int s = 0; s < 4; s++) {
                float* p = rout + b * 32 + s;  // (((b*2+c)*2+d)*2+r)*4+s
                p[0]  = Rn[s].x;  p[4]  = 0.f;        // R[0,0]
                p[8]  = Rn[s].z;  p[12] = Rn[s].w;    // R[0,1]
                p[16] = Rn[s].z;  p[20] = -Rn[s].w;   // R[1,0] = conj
                p[24] = Rn[s].y;  p[28] = 0.f;        // R[1,1]
            }
        }

#pragma unroll
        for (int k = KF - 1; k >= 0; k--) {
            int f = f0 + k * WARPS;
            if (f >= NF) continue;
            size_t p = (size_t)f * NB + b;
            float4 vv = vout[p];
            float4 xv = x[p];
            float va[4] = {vv.x, vv.y, vv.z, vv.w};

            float c00 = SQEPS, c11 = SQEPS, cre = 0.f, cim = 0.f;
#pragma unroll
            for (int s = 0; s < 4; s++) {
                c00 += va[s] * Rn[s].x;
                c11 += va[s] * Rn[s].y;
                cre += va[s] * Rn[s].z;
                cim += va[s] * Rn[s].w;
            }
            float det = c00 * c11 - (cre * cre + cim * cim);
            float id = 1.0f / det;
            float w0r = id * (c11 * xv.x - (cre * xv.z - cim * xv.w));
            float w0i = id * (c11 * xv.y - (cre * xv.w + cim * xv.z));
            float w1r = id * (c00 * xv.z - (cre * xv.x + cim * xv.y));
            float w1i = id * (c00 * xv.w - (cre * xv.y - cim * xv.x));

            float o0r[4], o0i[4], o1r[4], o1i[4];
#pragma unroll
            for (int s = 0; s < 4; s++) {
                o0r[s] = va[s] * (Rn[s].x * w0r + Rn[s].z * w1r - Rn[s].w * w1i);
                o0i[s] = va[s] * (Rn[s].x * w0i + Rn[s].z * w1i + Rn[s].w * w1r);
                o1r[s] = va[s] * (Rn[s].z * w0r + Rn[s].w * w0i + Rn[s].y * w1r);
                o1i[s] = va[s] * (Rn[s].z * w0i - Rn[s].w * w0r + Rn[s].y * w1i);
            }

            float4* po = yout + p * 4;
            __stcs(po + 0, make_float4(o0r[0], o0r[1], o0r[2], o0r[3]));
            __stcs(po + 1, make_float4(o0i[0], o0i[1], o0i[2], o0i[3]));
            __stcs(po + 2, make_float4(o1r[0], o1r[1], o1r[2], o1r[3]));
            __stcs(po + 3, make_float4(o1i[0], o1i[1], o1i[2], o1i[3]));
        }
    }

    // Reset g_acc1 for next replay (its last read was phase B)
    if (blockIdx.y == 0 && tid < 128) {
        int idx = blockIdx.x * 128 + tid;
        if (idx < NB * 4) g_acc1[idx] = make_float4(0.f, 0.f, 0.f, 0.f);
    }

    // Last block out resets barrier counters (graph-replay safe)
    if (tid == 0) {
        __threadfence();
        if (atomicAdd(&g_done, 1u) == (unsigned)(NBLK - 1)) {
            g_cnt1 = 0; g_cnt2 = 0; g_done = 0;
            __threadfence();
        }
    }
}

extern "C" void kernel_launch(void* const* d_in, const int* in_sizes, int n_in,
                              void* d_out, int out_size)
{
    const float4* y = (const float4*)d_in[0];
    const float4* x = (const float4*)d_in[1];
    float* out = (float*)d_out;

    float4* yout = (float4*)out;                                     // (F,B,C,2,S)
    float4* vout = (float4*)(out + (size_t)NF * NB * 16);            // (F,B,S)
    float*  rout = out + (size_t)NF * NB * 16 + (size_t)NF * NB * 4; // (B,C,C,2,S)

    dim3 blk(32, WARPS);
    dim3 grd(NBX, NTY);
    k_fused<<<grd, blk>>>(y, x, vout, yout, rout);
}

// round 7
// speedup vs baseline: 1.3586x; 1.0117x over previous
#include <cuda_runtime.h>

// Problem constants (fixed by setup_inputs)
#define NF 1000
#define NB 2049
#define EPSV 1.1920928955078125e-07f   // float32 eps
#define SQEPS 3.45266983e-04f          // sqrt(eps)

#define WARPS 8
#define KF 14                  // f-values per thread per phase
#define FPT (WARPS * KF)       // 112 f per tile
#define NBX 65                 // ceil(2049/32)
#define NTY 9                  // ceil(1000/112)
#define NBLK (NBX * NTY)       // 585 blocks; <= 592 resident @ 4 blocks/SM

// Accumulators (no cudaMalloc allowed). Zero-initialized at module load.
__device__ float4 g_acc1[NB * 4];
__device__ float4 g_acc2[NB * 4];

// Grid-barrier state; self-resetting (last block out zeroes everything).
__device__ unsigned g_cnt1 = 0, g_cnt2 = 0, g_done = 0;

__device__ __forceinline__ void cp16(float4* dst, const float4* src, int sz) {
    unsigned d = (unsigned)__cvta_generic_to_shared(dst);
    asm volatile("cp.async.cg.shared.global [%0], [%1], 16, %2;"
                 :: "r"(d), "l"(src), "r"(sz) : "memory");
}
#define CP_COMMIT() asm volatile("cp.async.commit_group;" ::: "memory")
#define CP_WAIT2()  asm volatile("cp.async.wait_group 2;" ::: "memory")
#define CP_WAIT0()  asm volatile("cp.async.wait_group 0;" ::: "memory")

__device__ __forceinline__ void grid_barrier(unsigned* cnt) {
    __syncthreads();
    __threadfence();
    if (threadIdx.x == 0 && threadIdx.y == 0) {
        atomicAdd(cnt, 1u);
        while (atomicAdd(cnt, 0u) < (unsigned)NBLK) { }
    }
    __syncthreads();
    __threadfence();
}

__device__ __forceinline__ float4 norm_acc(float4 a) {
    float inv = 1.0f / (EPSV + 0.5f * (a.x + a.y));
    return make_float4(a.x * inv, a.y * inv, a.z * inv, a.w * inv);
}

// Swizzled float4 slot inside a 32-row x 4-component warp tile.
// Conflict-free for: per-thread row access (LDS/STS of q_c at row=lane) AND
// linear coalesced access (j = r*32+lane -> row=j>>2, c=j&3). Verified by bank walk.
__device__ __forceinline__ int slot_of(int bl, int c) {
    return bl * 4 + ((c + (bl >> 1)) & 3);
}

// Issue one warp-tile (f, B0..B0+31) of y as 4 coalesced cp.async rounds.
__device__ __forceinline__ void issue_tile(const float4* __restrict__ y,
                                           int f, int B0, int lane, float4* st)
{
    const float4* base = y + ((size_t)(f < NF ? f : 0) * NB + B0) * 4;
#pragma unroll
    for (int r = 0; r < 4; r++) {
        int j = r * 32 + lane;
        int bl = j >> 2, c = j & 3;
        int ok = (f < NF && (B0 + bl) < NB) ? 16 : 0;   // OOB -> zero-fill
        cp16(st + slot_of(bl, c), base + j, ok);
    }
    CP_COMMIT();
}

// Block reduction over threadIdx.y (8 warps) + atomics into acc.
__device__ __forceinline__ void block_reduce_atomic(
    const float a00[4], const float a11[4], const float are[4], const float aim[4],
    int b, bool bok, float4* acc, float (*red)[32][17])
{
    int lane = threadIdx.x, ty = threadIdx.y;
    float* p = red[ty][lane];
#pragma unroll
    for (int s = 0; s < 4; s++) {
        p[s]      = a00[s];
        p[4 + s]  = a11[s];
        p[8 + s]  = are[s];
        p[12 + s] = aim[s];
    }
    __syncthreads();
#pragma unroll
    for (int st = WARPS / 2; st >= 1; st >>= 1) {
        if (ty < st) {
            float* q = red[ty + st][lane];
#pragma unroll
            for (int i = 0; i < 16; i++) p[i] += q[i];
        }
        __syncthreads();
    }
    if (ty == 0 && bok) {
#pragma unroll
        for (int s = 0; s < 4; s++) {
            float* dst = ((float*)acc) + (b * 4 + s) * 4;
            atomicAdd(dst + 0, p[s]);
            atomicAdd(dst + 1, p[4 + s]);
            atomicAdd(dst + 2, p[8 + s]);
            atomicAdd(dst + 3, p[12 + s]);
        }
    }
    __syncthreads();
}

__global__ void __launch_bounds__(256, 4) k_fused(
    const float4* __restrict__ y,
    const float4* __restrict__ x,
    float4* __restrict__ vout,
    float4* __restrict__ yout,
    float* __restrict__ rout)
{
    // 8 warps x 3 stages x 128 float4 = 48 KB; reduction buffer (17 KB) overlays it.
    __shared__ float4 sm_stage[WARPS][3][128];
    float (*red)[32][17] = (float(*)[32][17])(&sm_stage[0][0][0]);

    int lane = threadIdx.x, ty = threadIdx.y;
    int tid = ty * 32 + lane;
    int B0 = blockIdx.x * 32;
    int b = B0 + lane;
    bool bok = b < NB;
    int bc = bok ? b : 0;
    int f0 = blockIdx.y * FPT + ty;      // warp-uniform f base
    float4* stg = &sm_stage[ty][0][0];   // this warp's 3 stages (contiguous 3*128)

    // Reset g_acc2 for this run (accumulated in phase B, after barrier 1)
    if (blockIdx.y == 0 && tid < 128) {
        int idx = blockIdx.x * 128 + tid;
        if (idx < NB * 4) g_acc2[idx] = make_float4(0.f, 0.f, 0.f, 0.f);
    }

    // ================= Phase A: reduce |y|^2 / y y^H over f (branch-free) ======
    {
        float a00[4] = {0,0,0,0}, a11[4] = {0,0,0,0}, are[4] = {0,0,0,0}, aim[4] = {0,0,0,0};
        issue_tile(y, f0 + 0 * WARPS, B0, lane, stg + 0 * 128);
        issue_tile(y, f0 + 1 * WARPS, B0, lane, stg + 1 * 128);
        issue_tile(y, f0 + 2 * WARPS, B0, lane, stg + 2 * 128);
#pragma unroll
        for (int k = 0; k < KF; k++) {
            CP_WAIT2();
            __syncwarp();
            float4* s = stg + (k % 3) * 128;
            float4 q0 = s[slot_of(lane, 0)];
            float4 q1 = s[slot_of(lane, 1)];
            float4 q2 = s[slot_of(lane, 2)];
            float4 q3 = s[slot_of(lane, 3)];
            issue_tile(y, f0 + (k + 3) * WARPS, B0, lane, stg + ((k + 3) % 3) * 128);
#define ACC_S(i, c0r, c0i, c1r, c1i)              \
            a00[i] += c0r*c0r + c0i*c0i;          \
            a11[i] += c1r*c1r + c1i*c1i;          \
            are[i] += c0r*c1r + c0i*c1i;          \
            aim[i] += c0i*c1r - c0r*c1i;
            ACC_S(0, q0.x, q1.x, q2.x, q3.x)
            ACC_S(1, q0.y, q1.y, q2.y, q3.y)
            ACC_S(2, q0.z, q1.z, q2.z, q3.z)
            ACC_S(3, q0.w, q1.w, q2.w, q3.w)
#undef ACC_S
        }
        CP_WAIT0();
        __syncthreads();   // staging -> red overlay handoff (cross-warp)
        block_reduce_atomic(a00, a11, are, aim, b, bok, g_acc1, red);
    }
    grid_barrier(&g_cnt1);

    // ====== Phase B: apply iter-1 filter (y tile L2-hot), acc2, write vout ======
    {
        float a00[4] = {0,0,0,0}, a11[4] = {0,0,0,0}, are[4] = {0,0,0,0}, aim[4] = {0,0,0,0};
        float4 Rn[4];
#pragma unroll
        for (int s = 0; s < 4; s++) Rn[s] = norm_acc(g_acc1[bc * 4 + s]);

        issue_tile(y, f0 + 0 * WARPS, B0, lane, stg + 0 * 128);
        issue_tile(y, f0 + 1 * WARPS, B0, lane, stg + 1 * 128);
        issue_tile(y, f0 + 2 * WARPS, B0, lane, stg + 2 * 128);
#pragma unroll
        for (int k = 0; k < KF; k++) {
            int f = f0 + k * WARPS;
            size_t pidx = (size_t)(f < NF ? f : 0) * NB + bc;   // clamped, value unused if OOB
            float4 xv = __ldg(x + pidx);
            CP_WAIT2();
            __syncwarp();
            float4* sp = stg + (k % 3) * 128;
            float4 q0 = sp[slot_of(lane, 0)];
            float4 q1 = sp[slot_of(lane, 1)];
            float4 q2 = sp[slot_of(lane, 2)];
            float4 q3 = sp[slot_of(lane, 3)];
            issue_tile(y, f0 + (k + 3) * WARPS, B0, lane, stg + ((k + 3) % 3) * 128);

            float i0r[4] = {q0.x, q0.y, q0.z, q0.w};
            float i0i[4] = {q1.x, q1.y, q1.z, q1.w};
            float i1r[4] = {q2.x, q2.y, q2.z, q2.w};
            float i1i[4] = {q3.x, q3.y, q3.z, q3.w};

            float v[4];
            float c00 = SQEPS, c11 = SQEPS, cre = 0.f, cim = 0.f;
#pragma unroll
            for (int s = 0; s < 4; s++) {
                v[s] = 0.5f * (i0r[s]*i0r[s] + i0i[s]*i0i[s] + i1r[s]*i1r[s] + i1i[s]*i1i[s]);
                c00 += v[s] * Rn[s].x;
                c11 += v[s] * Rn[s].y;
                cre += v[s] * Rn[s].z;
                cim += v[s] * Rn[s].w;
            }
            float det = c00 * c11 - (cre * cre + cim * cim);
            float id = 1.0f / det;
            float w0r = id * (c11 * xv.x - (cre * xv.z - cim * xv.w));
            float w0i = id * (c11 * xv.y - (cre * xv.w + cim * xv.z));
            float w1r = id * (c00 * xv.z - (cre * xv.x + cim * xv.y));
            float w1i = id * (c00 * xv.w - (cre * xv.y - cim * xv.x));

            float v2[4];
#pragma unroll
            for (int s = 0; s < 4; s++) {
                float o0r = v[s] * (Rn[s].x * w0r + Rn[s].z * w1r - Rn[s].w * w1i);
                float o0i = v[s] * (Rn[s].x * w0i + Rn[s].z * w1i + Rn[s].w * w1r);
                float o1r = v[s] * (Rn[s].z * w0r + Rn[s].w * w0i + Rn[s].y * w1r);
                float o1i = v[s] * (Rn[s].z * w0i - Rn[s].w * w0r + Rn[s].y * w1i);
                float t00 = o0r*o0r + o0i*o0i;
                float t11 = o1r*o1r + o1i*o1i;
                a00[s] += t00;
                a11[s] += t11;
                are[s] += o0r*o1r + o0i*o1i;
                aim[s] += o0i*o1r - o0r*o1i;
                v2[s] = 0.5f * (t00 + t11);
            }
            if (bok && f < NF)   // regular store -> stays in L2 for phase C
                vout[(size_t)f * NB + b] = make_float4(v2[0], v2[1], v2[2], v2[3]);
        }
        CP_WAIT0();
        __syncthreads();
        block_reduce_atomic(a00, a11, are, aim, b, bok, g_acc2, red);
    }
    grid_barrier(&g_cnt2);

    // ====== Phase C: iter-2 filter from (vout, x) [L2-hot], coalesced y_out ======
    {
        float4 Rn[4];
#pragma unroll
        for (int s = 0; s < 4; s++) Rn[s] = norm_acc(g_acc2[bc * 4 + s]);

        if (blockIdx.y == 0 && ty == 0 && bok) {   // emit R_out (B, C, C, 2, S)
#pragma unroll
            for (int s = 0; s < 4; s++) {
                float* p = rout + b * 32 + s;
                p[0]  = Rn[s].x;  p[4]  = 0.f;        // R[0,0]
                p[8]  = Rn[s].z;  p[12] = Rn[s].w;    // R[0,1]
                p[16] = Rn[s].z;  p[20] = -Rn[s].w;   // R[1,0] = conj
                p[24] = Rn[s].y;  p[28] = 0.f;        // R[1,1]
            }
        }

        float4* sp = stg;   // warp-private staging (stage 0), free after barrier 2
#pragma unroll
        for (int k = 0; k < KF; k++) {
            int f = f0 + k * WARPS;
            bool fok = f < NF;                        // warp-uniform
            size_t pidx = (size_t)(fok ? f : 0) * NB + bc;
            float4 vv = vout[pidx];
            float4 xv = x[pidx];
            float va[4] = {vv.x, vv.y, vv.z, vv.w};

            float c00 = SQEPS, c11 = SQEPS, cre = 0.f, cim = 0.f;
#pragma unroll
            for (int s = 0; s < 4; s++) {
                c00 += va[s] * Rn[s].x;
                c11 += va[s] * Rn[s].y;
                cre += va[s] * Rn[s].z;
                cim += va[s] * Rn[s].w;
            }
            float det = c00 * c11 - (cre * cre + cim * cim);
            float id = 1.0f / det;
            float w0r = id * (c11 * xv.x - (cre * xv.z - cim * xv.w));
            float w0i = id * (c11 * xv.y - (cre * xv.w + cim * xv.z));
            float w1r = id * (c00 * xv.z - (cre * xv.x + cim * xv.y));
            float w1i = id * (c00 * xv.w - (cre * xv.y - cim * xv.x));

            float o0r[4], o0i[4], o1r[4], o1i[4];
#pragma unroll
            for (int s = 0; s < 4; s++) {
                o0r[s] = va[s] * (Rn[s].x * w0r + Rn[s].z * w1r - Rn[s].w * w1i);
                o0i[s] = va[s] * (Rn[s].x * w0i + Rn[s].z * w1i + Rn[s].w * w1r);
                o1r[s] = va[s] * (Rn[s].z * w0r + Rn[s].w * w0i + Rn[s].y * w1r);
                o1i[s] = va[s] * (Rn[s].z * w0i - Rn[s].w * w0r + Rn[s].y * w1i);
            }

            if (fok) {   // warp-uniform: smem transpose -> coalesced STG
                __syncwarp();
                sp[slot_of(lane, 0)] = make_float4(o0r[0], o0r[1], o0r[2], o0r[3]);
                sp[slot_of(lane, 1)] = make_float4(o0i[0], o0i[1], o0i[2], o0i[3]);
                sp[slot_of(lane, 2)] = make_float4(o1r[0], o1r[1], o1r[2], o1r[3]);
                sp[slot_of(lane, 3)] = make_float4(o1i[0], o1i[1], o1i[2], o1i[3]);
                __syncwarp();
                float4* base = yout + ((size_t)f * NB + B0) * 4;
#pragma unroll
                for (int r = 0; r < 4; r++) {
                    int j = r * 32 + lane;
                    int bl = j >> 2, c = j & 3;
                    if (B0 + bl < NB)
                        __stcs(base + j, sp[slot_of(bl, c)]);
                }
            }
        }
    }

    // Reset g_acc1 for next replay (its last read was phase B)
    if (blockIdx.y == 0 && tid < 128) {
        int idx = blockIdx.x * 128 + tid;
        if (idx < NB * 4) g_acc1[idx] = make_float4(0.f, 0.f, 0.f, 0.f);
    }

    // Last block out resets barrier counters (graph-replay safe)
    if (tid == 0) {
        __threadfence();
        if (atomicAdd(&g_done, 1u) == (unsigned)(NBLK - 1)) {
            g_cnt1 = 0; g_cnt2 = 0; g_done = 0;
            __threadfence();
        }
    }
}

extern "C" void kernel_launch(void* const* d_in, const int* in_sizes, int n_in,
                              void* d_out, int out_size)
{
    const float4* y = (const float4*)d_in[0];
    const float4* x = (const float4*)d_in[1];
    float* out = (float*)d_out;

    float4* yout = (float4*)out;                                     // (F,B,C,2,S)
    float4* vout = (float4*)(out + (size_t)NF * NB * 16);            // (F,B,S)
    float*  rout = out + (size_t)NF * NB * 16 + (size_t)NF * NB * 4; // (B,C,C,2,S)

    dim3 blk(32, WARPS);
    dim3 grd(NBX, NTY);
    k_fused<<<grd, blk>>>(y, x, vout, yout, rout);
}

// round 9
// speedup vs baseline: 1.6440x; 1.2101x over previous
#include <cuda_runtime.h>

// Problem constants (fixed by setup_inputs)
#define NF 1000
#define NB 2049
#define EPSV 1.1920928955078125e-07f   // float32 eps
#define SQEPS 3.45266983e-04f          // sqrt(eps)

#define WARPS 8
#define KF 14                  // f-values per thread per phase
#define FPT (WARPS * KF)       // 112 f per tile
#define NBX 65                 // ceil(2049/32)
#define NTY 9                  // ceil(1000/112)
#define NBLK (NBX * NTY)       // 585 blocks; <= 592 resident @ 4 blocks/SM

// Accumulators (no cudaMalloc allowed). Zero-initialized at module load.
__device__ float4 g_acc1[NB * 4];
__device__ float4 g_acc2[NB * 4];

// Grid-barrier state; self-resetting (last block out zeroes everything).
__device__ unsigned g_cnt1 = 0, g_cnt2 = 0, g_done = 0;

__device__ __forceinline__ void cp16(float4* dst, const float4* src, int sz) {
    unsigned d = (unsigned)__cvta_generic_to_shared(dst);
    asm volatile("cp.async.cg.shared.global [%0], [%1], 16, %2;"
                 :: "r"(d), "l"(src), "r"(sz) : "memory");
}
#define CP_COMMIT() asm volatile("cp.async.commit_group;" ::: "memory")
#define CP_WAIT2()  asm volatile("cp.async.wait_group 2;" ::: "memory")
#define CP_WAIT0()  asm volatile("cp.async.wait_group 0;" ::: "memory")

__device__ __forceinline__ void grid_barrier(unsigned* cnt) {
    __syncthreads();
    __threadfence();
    if (threadIdx.x == 0 && threadIdx.y == 0) {
        atomicAdd(cnt, 1u);
        while (atomicAdd(cnt, 0u) < (unsigned)NBLK) { }
    }
    __syncthreads();
    __threadfence();
}

__device__ __forceinline__ float4 norm_acc(float4 a) {
    float inv = 1.0f / (EPSV + 0.5f * (a.x + a.y));
    return make_float4(a.x * inv, a.y * inv, a.z * inv, a.w * inv);
}

// Swizzled float4 slot inside a 32-row x 4-component warp tile.
// Conflict-free for per-thread row access AND linear coalesced access.
__device__ __forceinline__ int slot_of(int bl, int c) {
    return bl * 4 + ((c + (bl >> 1)) & 3);
}

// Issue one warp-tile (f, B0..B0+31) of y as 4 coalesced cp.async rounds.
__device__ __forceinline__ void issue_tile(const float4* __restrict__ y,
                                           int f, int B0, int lane, float4* st)
{
    const float4* base = y + ((size_t)(f < NF ? f : 0) * NB + B0) * 4;
#pragma unroll
    for (int r = 0; r < 4; r++) {
        int j = r * 32 + lane;
        int bl = j >> 2, c = j & 3;
        int ok = (f < NF && (B0 + bl) < NB) ? 16 : 0;   // OOB -> zero-fill
        cp16(st + slot_of(bl, c), base + j, ok);
    }
    CP_COMMIT();
}

// Block reduction over threadIdx.y (8 warps) + atomics into acc.
__device__ __forceinline__ void block_reduce_atomic(
    const float a00[4], const float a11[4], const float are[4], const float aim[4],
    int b, bool bok, float4* acc, float (*red)[32][17])
{
    int lane = threadIdx.x, ty = threadIdx.y;
    float* p = red[ty][lane];
#pragma unroll
    for (int s = 0; s < 4; s++) {
        p[s]      = a00[s];
        p[4 + s]  = a11[s];
        p[8 + s]  = are[s];
        p[12 + s] = aim[s];
    }
    __syncthreads();
#pragma unroll
    for (int st = WARPS / 2; st >= 1; st >>= 1) {
        if (ty < st) {
            float* q = red[ty + st][lane];
#pragma unroll
            for (int i = 0; i < 16; i++) p[i] += q[i];
        }
        __syncthreads();
    }
    if (ty == 0 && bok) {
#pragma unroll
        for (int s = 0; s < 4; s++) {
            float* dst = ((float*)acc) + (b * 4 + s) * 4;
            atomicAdd(dst + 0, p[s]);
            atomicAdd(dst + 1, p[4 + s]);
            atomicAdd(dst + 2, p[8 + s]);
            atomicAdd(dst + 3, p[12 + s]);
        }
    }
    __syncthreads();
}

__global__ void __launch_bounds__(256, 4) k_fused(
    const float4* __restrict__ y,
    const float4* __restrict__ x,
    float4* __restrict__ vout,
    float4* __restrict__ yout,
    float* __restrict__ rout)
{
    // 8 warps x 3 stages x 128 float4 = 48 KB; reduction buffer (17 KB) overlays it.
    __shared__ float4 sm_stage[WARPS][3][128];
    float (*red)[32][17] = (float(*)[32][17])(&sm_stage[0][0][0]);

    int lane = threadIdx.x, ty = threadIdx.y;
    int tid = ty * 32 + lane;
    int B0 = blockIdx.x * 32;
    int b = B0 + lane;
    bool bok = b < NB;
    int bc = bok ? b : 0;
    int f0 = blockIdx.y * FPT + ty;      // warp-uniform f base
    float4* stg = &sm_stage[ty][0][0];   // this warp's 3 stages (contiguous 3*128)

    // Reset g_acc2 for this run (accumulated in phase B, after barrier 1)
    if (blockIdx.y == 0 && tid < 128) {
        int idx = blockIdx.x * 128 + tid;
        if (idx < NB * 4) g_acc2[idx] = make_float4(0.f, 0.f, 0.f, 0.f);
    }

    // ====== Phase A: reduce y y^H stats over f AND emit v1 into vout ==========
    // v1[f,b,s] = 0.5*(|y0|^2 + |y1|^2); phase B rebuilds yc1 from (v1, R1, x),
    // so y is never re-read. vout is overwritten with v2 in phase B.
    {
        float a00[4] = {0,0,0,0}, a11[4] = {0,0,0,0}, are[4] = {0,0,0,0}, aim[4] = {0,0,0,0};
        issue_tile(y, f0 + 0 * WARPS, B0, lane, stg + 0 * 128);
        issue_tile(y, f0 + 1 * WARPS, B0, lane, stg + 1 * 128);
        issue_tile(y, f0 + 2 * WARPS, B0, lane, stg + 2 * 128);
#pragma unroll
        for (int k = 0; k < KF; k++) {
            CP_WAIT2();
            __syncwarp();
            float4* s = stg + (k % 3) * 128;
            float4 q0 = s[slot_of(lane, 0)];
            float4 q1 = s[slot_of(lane, 1)];
            float4 q2 = s[slot_of(lane, 2)];
            float4 q3 = s[slot_of(lane, 3)];
            issue_tile(y, f0 + (k + 3) * WARPS, B0, lane, stg + ((k + 3) % 3) * 128);

            float v1[4];
#define ACC_S(i, c0r, c0i, c1r, c1i)              \
            { float t00 = c0r*c0r + c0i*c0i;      \
              float t11 = c1r*c1r + c1i*c1i;      \
              a00[i] += t00;                      \
              a11[i] += t11;                      \
              are[i] += c0r*c1r + c0i*c1i;        \
              aim[i] += c0i*c1r - c0r*c1i;        \
              v1[i] = 0.5f * (t00 + t11); }
            ACC_S(0, q0.x, q1.x, q2.x, q3.x)
            ACC_S(1, q0.y, q1.y, q2.y, q3.y)
            ACC_S(2, q0.z, q1.z, q2.z, q3.z)
            ACC_S(3, q0.w, q1.w, q2.w, q3.w)
#undef ACC_S
            int f = f0 + k * WARPS;
            if (bok && f < NF)   // regular store -> stays in L2 for phase B
                vout[(size_t)f * NB + b] = make_float4(v1[0], v1[1], v1[2], v1[3]);
        }
        CP_WAIT0();
        __syncthreads();   // staging -> red overlay handoff (cross-warp)
        block_reduce_atomic(a00, a11, are, aim, b, bok, g_acc1, red);
    }
    grid_barrier(&g_cnt1);

    // ====== Phase B: rebuild yc1 from (v1, R1, x); accumulate R2; v2 -> vout ===
    {
        float a00[4] = {0,0,0,0}, a11[4] = {0,0,0,0}, are[4] = {0,0,0,0}, aim[4] = {0,0,0,0};
        float4 Rn[4];
#pragma unroll
        for (int s = 0; s < 4; s++) Rn[s] = norm_acc(g_acc1[bc * 4 + s]);

#pragma unroll
        for (int k = KF - 1; k >= 0; k--) {     // reverse: hit freshest v1 lines first
            int f = f0 + k * WARPS;
            bool ok = bok && f < NF;
            size_t pidx = (size_t)(f < NF ? f : 0) * NB + bc;
            float4 vv = vout[pidx];             // v1 (L2-hot from phase A)
            float4 xv = x[pidx];
            float v[4] = {vv.x, vv.y, vv.z, vv.w};

            float c00 = SQEPS, c11 = SQEPS, cre = 0.f, cim = 0.f;
#pragma unroll
            for (int s = 0; s < 4; s++) {
                c00 += v[s] * Rn[s].x;
                c11 += v[s] * Rn[s].y;
                cre += v[s] * Rn[s].z;
                cim += v[s] * Rn[s].w;
            }
            float det = c00 * c11 - (cre * cre + cim * cim);
            float id = 1.0f / det;
            float w0r = id * (c11 * xv.x - (cre * xv.z - cim * xv.w));
            float w0i = id * (c11 * xv.y - (cre * xv.w + cim * xv.z));
            float w1r = id * (c00 * xv.z - (cre * xv.x + cim * xv.y));
            float w1i = id * (c00 * xv.w - (cre * xv.y - cim * xv.x));

            float v2[4];
#pragma unroll
            for (int s = 0; s < 4; s++) {
                float o0r = v[s] * (Rn[s].x * w0r + Rn[s].z * w1r - Rn[s].w * w1i);
                float o0i = v[s] * (Rn[s].x * w0i + Rn[s].z * w1i + Rn[s].w * w1r);
                float o1r = v[s] * (Rn[s].z * w0r + Rn[s].w * w0i + Rn[s].y * w1r);
                float o1i = v[s] * (Rn[s].z * w0i - Rn[s].w * w0r + Rn[s].y * w1i);
                float t00 = o0r*o0r + o0i*o0i;
                float t11 = o1r*o1r + o1i*o1i;
                if (ok) {            // keep OOB lanes out of the accumulators
                    a00[s] += t00;
                    a11[s] += t11;
                    are[s] += o0r*o1r + o0i*o1i;
                    aim[s] += o0i*o1r - o0r*o1i;
                }
                v2[s] = 0.5f * (t00 + t11);
            }
            if (ok)   // overwrite v1 with v2; stays in L2 for phase C
                vout[(size_t)f * NB + b] = make_float4(v2[0], v2[1], v2[2], v2[3]);
        }
        block_reduce_atomic(a00, a11, are, aim, b, bok, g_acc2, red);
    }
    grid_barrier(&g_cnt2);

    // ====== Phase C: iter-2 filter from (v2, x) [L2-hot], coalesced y_out ======
    {
        float4 Rn[4];
#pragma unroll
        for (int s = 0; s < 4; s++) Rn[s] = norm_acc(g_acc2[bc * 4 + s]);

        if (blockIdx.y == 0 && ty == 0 && bok) {   // emit R_out (B, C, C, 2, S)
#pragma unroll
            for (int s = 0; s < 4; s++) {
                float* p = rout + b * 32 + s;
                p[0]  = Rn[s].x;  p[4]  = 0.f;        // R[0,0]
                p[8]  = Rn[s].z;  p[12] = Rn[s].w;    // R[0,1]
                p[16] = Rn[s].z;  p[20] = -Rn[s].w;   // R[1,0] = conj
                p[24] = Rn[s].y;  p[28] = 0.f;        // R[1,1]
            }
        }

        float4* sp = stg;   // warp-private staging (stage 0), free after barrier 2
#pragma unroll
        for (int k = 0; k < KF; k++) {
            int f = f0 + k * WARPS;
            bool fok = f < NF;                        // warp-uniform
            size_t pidx = (size_t)(fok ? f : 0) * NB + bc;
            float4 vv = vout[pidx];
            float4 xv = x[pidx];
            float va[4] = {vv.x, vv.y, vv.z, vv.w};

            float c00 = SQEPS, c11 = SQEPS, cre = 0.f, cim = 0.f;
#pragma unroll
            for (int s = 0; s < 4; s++) {
                c00 += va[s] * Rn[s].x;
                c11 += va[s] * Rn[s].y;
                cre += va[s] * Rn[s].z;
                cim += va[s] * Rn[s].w;
            }
            float det = c00 * c11 - (cre * cre + cim * cim);
            float id = 1.0f / det;
            float w0r = id * (c11 * xv.x - (cre * xv.z - cim * xv.w));
            float w0i = id * (c11 * xv.y - (cre * xv.w + cim * xv.z));
            float w1r = id * (c00 * xv.z - (cre * xv.x + cim * xv.y));
            float w1i = id * (c00 * xv.w - (cre * xv.y - cim * xv.x));

            float o0r[4], o0i[4], o1r[4], o1i[4];
#pragma unroll
            for (int s = 0; s < 4; s++) {
                o0r[s] = va[s] * (Rn[s].x * w0r + Rn[s].z * w1r - Rn[s].w * w1i);
                o0i[s] = va[s] * (Rn[s].x * w0i + Rn[s].z * w1i + Rn[s].w * w1r);
                o1r[s] = va[s] * (Rn[s].z * w0r + Rn[s].w * w0i + Rn[s].y * w1r);
                o1i[s] = va[s] * (Rn[s].z * w0i - Rn[s].w * w0r + Rn[s].y * w1i);
            }

            if (fok) {   // warp-uniform: smem transpose -> coalesced STG
                __syncwarp();
                sp[slot_of(lane, 0)] = make_float4(o0r[0], o0r[1], o0r[2], o0r[3]);
                sp[slot_of(lane, 1)] = make_float4(o0i[0], o0i[1], o0i[2], o0i[3]);
                sp[slot_of(lane, 2)] = make_float4(o1r[0], o1r[1], o1r[2], o1r[3]);
                sp[slot_of(lane, 3)] = make_float4(o1i[0], o1i[1], o1i[2], o1i[3]);
                __syncwarp();
                float4* base = yout + ((size_t)f * NB + B0) * 4;
#pragma unroll
                for (int r = 0; r < 4; r++) {
                    int j = r * 32 + lane;
                    int bl = j >> 2, c = j & 3;
                    if (B0 + bl < NB)
                        __stcs(base + j, sp[slot_of(bl, c)]);
                }
            }
        }
    }

    // Reset g_acc1 for next replay (its last read was phase B)
    if (blockIdx.y == 0 && tid < 128) {
        int idx = blockIdx.x * 128 + tid;
        if (idx < NB * 4) g_acc1[idx] = make_float4(0.f, 0.f, 0.f, 0.f);
    }

    // Last block out resets barrier counters (graph-replay safe)
    if (tid == 0) {
        __threadfence();
        if (atomicAdd(&g_done, 1u) == (unsigned)(NBLK - 1)) {
            g_cnt1 = 0; g_cnt2 = 0; g_done = 0;
            __threadfence();
        }
    }
}

extern "C" void kernel_launch(void* const* d_in, const int* in_sizes, int n_in,
                              void* d_out, int out_size)
{
    const float4* y = (const float4*)d_in[0];
    const float4* x = (const float4*)d_in[1];
    float* out = (float*)d_out;

    float4* yout = (float4*)out;                                     // (F,B,C,2,S)
    float4* vout = (float4*)(out + (size_t)NF * NB * 16);            // (F,B,S)
    float*  rout = out + (size_t)NF * NB * 16 + (size_t)NF * NB * 4; // (B,C,C,2,S)

    dim3 blk(32, WARPS);
    dim3 grd(NBX, NTY);
    k_fused<<<grd, blk>>>(y, x, vout, yout, rout);
}

// round 10
// speedup vs baseline: 1.6846x; 1.0247x over previous
#include <cuda_runtime.h>

// Problem constants (fixed by setup_inputs)
#define NF 1000
#define NB 2049
#define EPSV 1.1920928955078125e-07f   // float32 eps
#define SQEPS 3.45266983e-04f          // sqrt(eps)

#define WARPS 8
#define KF 14                  // f-values per thread per phase
#define FPT (WARPS * KF)       // 112 f per tile
#define NBX 65                 // ceil(2049/32)
#define NTY 9                  // ceil(1000/112)
#define NBLK (NBX * NTY)       // 585 blocks; <= 592 resident @ 4 blocks/SM

// Accumulators (no cudaMalloc allowed). Zero-initialized at module load.
__device__ float4 g_acc1[NB * 4];
__device__ float4 g_acc2[NB * 4];

// Per-b-column barrier state (one 128B-padded counter per bx group).
// Group bx = the NTY blocks sharing blockIdx.x; they are the ONLY writers of
// g_acc*[bx*32 .. bx*32+31], so phases only need group-local synchronization.
// Self-resetting via per-group done counter (last of NTY out resets).
__device__ unsigned g_bar1[NBX * 32];
__device__ unsigned g_bar2[NBX * 32];
__device__ unsigned g_fin [NBX * 32];

__device__ __forceinline__ void cp16(float4* dst, const float4* src, int sz) {
    unsigned d = (unsigned)__cvta_generic_to_shared(dst);
    asm volatile("cp.async.cg.shared.global [%0], [%1], 16, %2;"
                 :: "r"(d), "l"(src), "r"(sz) : "memory");
}
#define CP_COMMIT() asm volatile("cp.async.commit_group;" ::: "memory")
#define CP_WAIT2()  asm volatile("cp.async.wait_group 2;" ::: "memory")
#define CP_WAIT0()  asm volatile("cp.async.wait_group 0;" ::: "memory")

// Group barrier: NTY arrivals on this group's counter.
__device__ __forceinline__ void group_barrier(unsigned* cnt) {
    __syncthreads();
    __threadfence();
    if (threadIdx.x == 0 && threadIdx.y == 0) {
        atomicAdd(cnt, 1u);
        while (atomicAdd(cnt, 0u) < (unsigned)NTY) __nanosleep(32);
    }
    __syncthreads();
    __threadfence();
}

__device__ __forceinline__ float4 norm_acc(float4 a) {
    float inv = 1.0f / (EPSV + 0.5f * (a.x + a.y));
    return make_float4(a.x * inv, a.y * inv, a.z * inv, a.w * inv);
}

// Swizzled float4 slot inside a 32-row x 4-component warp tile.
// Conflict-free for per-thread row access AND linear coalesced access.
__device__ __forceinline__ int slot_of(int bl, int c) {
    return bl * 4 + ((c + (bl >> 1)) & 3);
}

// Issue one warp-tile (f, B0..B0+31) of y as 4 coalesced cp.async rounds.
__device__ __forceinline__ void issue_tile(const float4* __restrict__ y,
                                           int f, int B0, int lane, float4* st)
{
    const float4* base = y + ((size_t)(f < NF ? f : 0) * NB + B0) * 4;
#pragma unroll
    for (int r = 0; r < 4; r++) {
        int j = r * 32 + lane;
        int bl = j >> 2, c = j & 3;
        int ok = (f < NF && (B0 + bl) < NB) ? 16 : 0;   // OOB -> zero-fill
        cp16(st + slot_of(bl, c), base + j, ok);
    }
    CP_COMMIT();
}

// Block reduction over threadIdx.y (8 warps) + atomics into acc.
__device__ __forceinline__ void block_reduce_atomic(
    const float a00[4], const float a11[4], const float are[4], const float aim[4],
    int b, bool bok, float4* acc, float (*red)[32][17])
{
    int lane = threadIdx.x, ty = threadIdx.y;
    float* p = red[ty][lane];
#pragma unroll
    for (int s = 0; s < 4; s++) {
        p[s]      = a00[s];
        p[4 + s]  = a11[s];
        p[8 + s]  = are[s];
        p[12 + s] = aim[s];
    }
    __syncthreads();
#pragma unroll
    for (int st = WARPS / 2; st >= 1; st >>= 1) {
        if (ty < st) {
            float* q = red[ty + st][lane];
#pragma unroll
            for (int i = 0; i < 16; i++) p[i] += q[i];
        }
        __syncthreads();
    }
    if (ty == 0 && bok) {
#pragma unroll
        for (int s = 0; s < 4; s++) {
            float* dst = ((float*)acc) + (b * 4 + s) * 4;
            atomicAdd(dst + 0, p[s]);
            atomicAdd(dst + 1, p[4 + s]);
            atomicAdd(dst + 2, p[8 + s]);
            atomicAdd(dst + 3, p[12 + s]);
        }
    }
    __syncthreads();
}

__global__ void __launch_bounds__(256, 4) k_fused(
    const float4* __restrict__ y,
    const float4* __restrict__ x,
    float4* __restrict__ vout,
    float4* __restrict__ yout,
    float* __restrict__ rout)
{
    // 8 warps x 3 stages x 128 float4 = 48 KB; reduction buffer (17 KB) overlays it.
    __shared__ float4 sm_stage[WARPS][3][128];
    float (*red)[32][17] = (float(*)[32][17])(&sm_stage[0][0][0]);

    int lane = threadIdx.x, ty = threadIdx.y;
    int tid = ty * 32 + lane;
    int bx = blockIdx.x;
    int B0 = bx * 32;
    int b = B0 + lane;
    bool bok = b < NB;
    int bc = bok ? b : 0;
    int f0 = blockIdx.y * FPT + ty;      // warp-uniform f base
    float4* stg = &sm_stage[ty][0][0];   // this warp's 3 stages (contiguous 3*128)

    unsigned* bar1 = &g_bar1[bx * 32];
    unsigned* bar2 = &g_bar2[bx * 32];
    unsigned* fin  = &g_fin [bx * 32];

    // Reset this group's g_acc2 slice (happens before our barrier-1 arrival,
    // hence before any group member's phase-B atomics).
    if (blockIdx.y == 0 && tid < 128) {
        g_acc2[bx * 128 + tid] = make_float4(0.f, 0.f, 0.f, 0.f);
    }

    // ====== Phase A: reduce y y^H stats over f AND emit v1 into vout ==========
    {
        float a00[4] = {0,0,0,0}, a11[4] = {0,0,0,0}, are[4] = {0,0,0,0}, aim[4] = {0,0,0,0};
        issue_tile(y, f0 + 0 * WARPS, B0, lane, stg + 0 * 128);
        issue_tile(y, f0 + 1 * WARPS, B0, lane, stg + 1 * 128);
        issue_tile(y, f0 + 2 * WARPS, B0, lane, stg + 2 * 128);
#pragma unroll
        for (int k = 0; k < KF; k++) {
            CP_WAIT2();
            __syncwarp();
            float4* s = stg + (k % 3) * 128;
            float4 q0 = s[slot_of(lane, 0)];
            float4 q1 = s[slot_of(lane, 1)];
            float4 q2 = s[slot_of(lane, 2)];
            float4 q3 = s[slot_of(lane, 3)];
            issue_tile(y, f0 + (k + 3) * WARPS, B0, lane, stg + ((k + 3) % 3) * 128);

            float v1[4];
#define ACC_S(i, c0r, c0i, c1r, c1i)              \
            { float t00 = c0r*c0r + c0i*c0i;      \
              float t11 = c1r*c1r + c1i*c1i;      \
              a00[i] += t00;                      \
              a11[i] += t11;                      \
              are[i] += c0r*c1r + c0i*c1i;        \
              aim[i] += c0i*c1r - c0r*c1i;        \
              v1[i] = 0.5f * (t00 + t11); }
            ACC_S(0, q0.x, q1.x, q2.x, q3.x)
            ACC_S(1, q0.y, q1.y, q2.y, q3.y)
            ACC_S(2, q0.z, q1.z, q2.z, q3.z)
            ACC_S(3, q0.w, q1.w, q2.w, q3.w)
#undef ACC_S
            int f = f0 + k * WARPS;
            if (bok && f < NF)   // regular store -> stays in L2 for phase B
                vout[(size_t)f * NB + b] = make_float4(v1[0], v1[1], v1[2], v1[3]);
        }
        CP_WAIT0();
        __syncthreads();   // staging -> red overlay handoff (cross-warp)
        block_reduce_atomic(a00, a11, are, aim, b, bok, g_acc1, red);
    }
    group_barrier(bar1);   // only the NTY blocks sharing bx

    // ====== Phase B: rebuild yc1 from (v1, R1, x); accumulate R2; v2 -> vout ===
    {
        float a00[4] = {0,0,0,0}, a11[4] = {0,0,0,0}, are[4] = {0,0,0,0}, aim[4] = {0,0,0,0};
        float4 Rn[4];
#pragma unroll
        for (int s = 0; s < 4; s++) Rn[s] = norm_acc(g_acc1[bc * 4 + s]);

#pragma unroll
        for (int k = KF - 1; k >= 0; k--) {     // reverse: hit freshest v1 lines first
            int f = f0 + k * WARPS;
            bool ok = bok && f < NF;
            size_t pidx = (size_t)(f < NF ? f : 0) * NB + bc;
            float4 vv = vout[pidx];             // v1 (L2-hot from phase A)
            float4 xv = x[pidx];
            float v[4] = {vv.x, vv.y, vv.z, vv.w};

            float c00 = SQEPS, c11 = SQEPS, cre = 0.f, cim = 0.f;
#pragma unroll
            for (int s = 0; s < 4; s++) {
                c00 += v[s] * Rn[s].x;
                c11 += v[s] * Rn[s].y;
                cre += v[s] * Rn[s].z;
                cim += v[s] * Rn[s].w;
            }
            float det = c00 * c11 - (cre * cre + cim * cim);
            float id = 1.0f / det;
            float w0r = id * (c11 * xv.x - (cre * xv.z - cim * xv.w));
            float w0i = id * (c11 * xv.y - (cre * xv.w + cim * xv.z));
            float w1r = id * (c00 * xv.z - (cre * xv.x + cim * xv.y));
            float w1i = id * (c00 * xv.w - (cre * xv.y - cim * xv.x));

            float v2[4];
#pragma unroll
            for (int s = 0; s < 4; s++) {
                float o0r = v[s] * (Rn[s].x * w0r + Rn[s].z * w1r - Rn[s].w * w1i);
                float o0i = v[s] * (Rn[s].x * w0i + Rn[s].z * w1i + Rn[s].w * w1r);
                float o1r = v[s] * (Rn[s].z * w0r + Rn[s].w * w0i + Rn[s].y * w1r);
                float o1i = v[s] * (Rn[s].z * w0i - Rn[s].w * w0r + Rn[s].y * w1i);
                float t00 = o0r*o0r + o0i*o0i;
                float t11 = o1r*o1r + o1i*o1i;
                if (ok) {            // keep OOB lanes out of the accumulators
                    a00[s] += t00;
                    a11[s] += t11;
                    are[s] += o0r*o1r + o0i*o1i;
                    aim[s] += o0i*o1r - o0r*o1i;
                }
                v2[s] = 0.5f * (t00 + t11);
            }
            if (ok)   // overwrite v1 with v2; stays in L2 for phase C
                vout[(size_t)f * NB + b] = make_float4(v2[0], v2[1], v2[2], v2[3]);
        }
        block_reduce_atomic(a00, a11, are, aim, b, bok, g_acc2, red);
    }
    group_barrier(bar2);

    // ====== Phase C: iter-2 filter from (v2, x) [L2-hot], coalesced y_out ======
    {
        float4 Rn[4];
#pragma unroll
        for (int s = 0; s < 4; s++) Rn[s] = norm_acc(g_acc2[bc * 4 + s]);

        if (blockIdx.y == 0 && ty == 0 && bok) {   // emit R_out (B, C, C, 2, S)
#pragma unroll
            for (int s = 0; s < 4; s++) {
                float* p = rout + b * 32 + s;
                p[0]  = Rn[s].x;  p[4]  = 0.f;        // R[0,0]
                p[8]  = Rn[s].z;  p[12] = Rn[s].w;    // R[0,1]
                p[16] = Rn[s].z;  p[20] = -Rn[s].w;   // R[1,0] = conj
                p[24] = Rn[s].y;  p[28] = 0.f;        // R[1,1]
            }
        }

        float4* sp = stg;   // warp-private staging (stage 0), free after barrier 2
#pragma unroll
        for (int k = 0; k < KF; k++) {
            int f = f0 + k * WARPS;
            bool fok = f < NF;                        // warp-uniform
            size_t pidx = (size_t)(fok ? f : 0) * NB + bc;
            float4 vv = vout[pidx];
            float4 xv = x[pidx];
            float va[4] = {vv.x, vv.y, vv.z, vv.w};

            float c00 = SQEPS, c11 = SQEPS, cre = 0.f, cim = 0.f;
#pragma unroll
            for (int s = 0; s < 4; s++) {
                c00 += va[s] * Rn[s].x;
                c11 += va[s] * Rn[s].y;
                cre += va[s] * Rn[s].z;
                cim += va[s] * Rn[s].w;
            }
            float det = c00 * c11 - (cre * cre + cim * cim);
            float id = 1.0f / det;
            float w0r = id * (c11 * xv.x - (cre * xv.z - cim * xv.w));
            float w0i = id * (c11 * xv.y - (cre * xv.w + cim * xv.z));
            float w1r = id * (c00 * xv.z - (cre * xv.x + cim * xv.y));
            float w1i = id * (c00 * xv.w - (cre * xv.y - cim * xv.x));

            float o0r[4], o0i[4], o1r[4], o1i[4];
#pragma unroll
            for (int s = 0; s < 4; s++) {
                o0r[s] = va[s] * (Rn[s].x * w0r + Rn[s].z * w1r - Rn[s].w * w1i);
                o0i[s] = va[s] * (Rn[s].x * w0i + Rn[s].z * w1i + Rn[s].w * w1r);
                o1r[s] = va[s] * (Rn[s].z * w0r + Rn[s].w * w0i + Rn[s].y * w1r);
                o1i[s] = va[s] * (Rn[s].z * w0i - Rn[s].w * w0r + Rn[s].y * w1i);
            }

            if (fok) {   // warp-uniform: smem transpose -> coalesced STG
                __syncwarp();
                sp[slot_of(lane, 0)] = make_float4(o0r[0], o0r[1], o0r[2], o0r[3]);
                sp[slot_of(lane, 1)] = make_float4(o0i[0], o0i[1], o0i[2], o0i[3]);
                sp[slot_of(lane, 2)] = make_float4(o1r[0], o1r[1], o1r[2], o1r[3]);
                sp[slot_of(lane, 3)] = make_float4(o1i[0], o1i[1], o1i[2], o1i[3]);
                __syncwarp();
                float4* base = yout + ((size_t)f * NB + B0) * 4;
#pragma unroll
                for (int r = 0; r < 4; r++) {
                    int j = r * 32 + lane;
                    int bl = j >> 2, c = j & 3;
                    if (B0 + bl < NB)
                        __stcs(base + j, sp[slot_of(bl, c)]);
                }
            }
        }
    }

    // Reset this group's g_acc1 slice for the next replay (its last read was
    // phase B; all group members passed barrier 2, so reads are done).
    if (blockIdx.y == 0 && tid < 128) {
        g_acc1[bx * 128 + tid] = make_float4(0.f, 0.f, 0.f, 0.f);
    }

    // Last of the NTY group blocks out resets the group's barrier counters.
    if (tid == 0) {
        __threadfence();
        if (atomicAdd(fin, 1u) == (unsigned)(NTY - 1)) {
            *bar1 = 0; *bar2 = 0; *fin = 0;
            __threadfence();
        }
    }
}

extern "C" void kernel_launch(void* const* d_in, const int* in_sizes, int n_in,
                              void* d_out, int out_size)
{
    const float4* y = (const float4*)d_in[0];
    const float4* x = (const float4*)d_in[1];
    float* out = (float*)d_out;

    float4* yout = (float4*)out;                                     // (F,B,C,2,S)
    float4* vout = (float4*)(out + (size_t)NF * NB * 16);            // (F,B,S)
    float*  rout = out + (size_t)NF * NB * 16 + (size_t)NF * NB * 4; // (B,C,C,2,S)

    dim3 blk(32, WARPS);
    dim3 grd(NBX, NTY);
    k_fused<<<grd, blk>>>(y, x, vout, yout, rout);
}

// round 11
// speedup vs baseline: 1.7246x; 1.0238x over previous
#include <cuda_runtime.h>

// Problem constants (fixed by setup_inputs)
#define NF 1000
#define NB 2049
#define EPSV 1.1920928955078125e-07f   // float32 eps
#define SQEPS 3.45266983e-04f          // sqrt(eps)

#define WARPS 8
#define KF 14                  // f-values per thread per phase
#define FPT (WARPS * KF)       // 112 f per tile
#define NBX 65                 // ceil(2049/32)
#define NTY 9                  // ceil(1000/112)
#define NBLK (NBX * NTY)       // 585 blocks; <= 592 resident @ 4 blocks/SM

// Accumulators (no cudaMalloc allowed). Zero-initialized at module load.
__device__ float4 g_acc1[NB * 4];
__device__ float4 g_acc2[NB * 4];

// Per-b-column barrier state (one padded counter per bx group).
__device__ unsigned g_bar1[NBX * 32];
__device__ unsigned g_bar2[NBX * 32];
__device__ unsigned g_fin [NBX * 32];

__device__ __forceinline__ void cp16(float4* dst, const float4* src, int sz) {
    unsigned d = (unsigned)__cvta_generic_to_shared(dst);
    asm volatile("cp.async.cg.shared.global [%0], [%1], 16, %2;"
                 :: "r"(d), "l"(src), "r"(sz) : "memory");
}
#define CP_COMMIT() asm volatile("cp.async.commit_group;" ::: "memory")
#define CP_WAIT2()  asm volatile("cp.async.wait_group 2;" ::: "memory")
#define CP_WAIT0()  asm volatile("cp.async.wait_group 0;" ::: "memory")

// Group barrier: NTY arrivals on this group's counter.
__device__ __forceinline__ void group_barrier(unsigned* cnt) {
    __syncthreads();
    __threadfence();
    if (threadIdx.x == 0 && threadIdx.y == 0) {
        atomicAdd(cnt, 1u);
        while (atomicAdd(cnt, 0u) < (unsigned)NTY) __nanosleep(32);
    }
    __syncthreads();
    __threadfence();
}

__device__ __forceinline__ float4 norm_acc(float4 a) {
    float inv = 1.0f / (EPSV + 0.5f * (a.x + a.y));
    return make_float4(a.x * inv, a.y * inv, a.z * inv, a.w * inv);
}

// Swizzled float4 slot inside a 32-row x 4-component warp tile.
__device__ __forceinline__ int slot_of(int bl, int c) {
    return bl * 4 + ((c + (bl >> 1)) & 3);
}

// Phase A: issue one warp-tile (f, B0..B0+31) of y as 4 coalesced cp.async rounds.
__device__ __forceinline__ void issue_tile(const float4* __restrict__ y,
                                           int f, int B0, int lane, float4* st)
{
    const float4* base = y + ((size_t)(f < NF ? f : 0) * NB + B0) * 4;
#pragma unroll
    for (int r = 0; r < 4; r++) {
        int j = r * 32 + lane;
        int bl = j >> 2, c = j & 3;
        int ok = (f < NF && (B0 + bl) < NB) ? 16 : 0;   // OOB -> zero-fill
        cp16(st + slot_of(bl, c), base + j, ok);
    }
    CP_COMMIT();
}

// Phases B/C: stage (vout, x) row f. Lane-private slots: st[lane] = v, st[32+lane] = x.
__device__ __forceinline__ void issue_vx(const float4* __restrict__ v,
                                         const float4* __restrict__ xx,
                                         int f, int B0, int lane, float4* st)
{
    bool fok = (f >= 0 && f < NF);
    size_t row = (size_t)(fok ? f : 0) * NB + B0;
    int ok = (fok && (B0 + lane) < NB) ? 16 : 0;        // OOB -> zero-fill
    cp16(st + lane,      v  + row + lane, ok);
    cp16(st + 32 + lane, xx + row + lane, ok);
    CP_COMMIT();
}

// Block reduction over threadIdx.y (8 warps) + atomics into acc.
__device__ __forceinline__ void block_reduce_atomic(
    const float a00[4], const float a11[4], const float are[4], const float aim[4],
    int b, bool bok, float4* acc, float (*red)[32][17])
{
    int lane = threadIdx.x, ty = threadIdx.y;
    float* p = red[ty][lane];
#pragma unroll
    for (int s = 0; s < 4; s++) {
        p[s]      = a00[s];
        p[4 + s]  = a11[s];
        p[8 + s]  = are[s];
        p[12 + s] = aim[s];
    }
    __syncthreads();
#pragma unroll
    for (int st = WARPS / 2; st >= 1; st >>= 1) {
        if (ty < st) {
            float* q = red[ty + st][lane];
#pragma unroll
            for (int i = 0; i < 16; i++) p[i] += q[i];
        }
        __syncthreads();
    }
    if (ty == 0 && bok) {
#pragma unroll
        for (int s = 0; s < 4; s++) {
            float* dst = ((float*)acc) + (b * 4 + s) * 4;
            atomicAdd(dst + 0, p[s]);
            atomicAdd(dst + 1, p[4 + s]);
            atomicAdd(dst + 2, p[8 + s]);
            atomicAdd(dst + 3, p[12 + s]);
        }
    }
    __syncthreads();
}

__global__ void __launch_bounds__(256, 4) k_fused(
    const float4* __restrict__ y,
    const float4* __restrict__ x,
    float4* __restrict__ vout,
    float4* __restrict__ yout,
    float* __restrict__ rout)
{
    // Per-warp 384-float4 region (6 KB). Phase A: 3 stages x 128.
    // Phases B/C: 3 stages x 64 (vx staging) at [0..191] + transpose at [192..319].
    // Reduction buffer (17 KB) overlays the whole thing between phases.
    __shared__ float4 sm[WARPS][384];
    float (*red)[32][17] = (float(*)[32][17])(&sm[0][0]);

    int lane = threadIdx.x, ty = threadIdx.y;
    int tid = ty * 32 + lane;
    int bx = blockIdx.x;
    int B0 = bx * 32;
    int b = B0 + lane;
    bool bok = b < NB;
    int bc = bok ? b : 0;
    int f0 = blockIdx.y * FPT + ty;      // warp-uniform f base
    float4* stg = &sm[ty][0];

    unsigned* bar1 = &g_bar1[bx * 32];
    unsigned* bar2 = &g_bar2[bx * 32];
    unsigned* fin  = &g_fin [bx * 32];

    // Reset this group's g_acc2 slice (before our barrier-1 arrival).
    if (blockIdx.y == 0 && tid < 128) {
        g_acc2[bx * 128 + tid] = make_float4(0.f, 0.f, 0.f, 0.f);
    }

    // ====== Phase A: reduce y y^H stats over f AND emit v1 into vout ==========
    {
        float a00[4] = {0,0,0,0}, a11[4] = {0,0,0,0}, are[4] = {0,0,0,0}, aim[4] = {0,0,0,0};
        issue_tile(y, f0 + 0 * WARPS, B0, lane, stg + 0 * 128);
        issue_tile(y, f0 + 1 * WARPS, B0, lane, stg + 1 * 128);
        issue_tile(y, f0 + 2 * WARPS, B0, lane, stg + 2 * 128);
#pragma unroll
        for (int k = 0; k < KF; k++) {
            CP_WAIT2();
            __syncwarp();
            float4* s = stg + (k % 3) * 128;
            float4 q0 = s[slot_of(lane, 0)];
            float4 q1 = s[slot_of(lane, 1)];
            float4 q2 = s[slot_of(lane, 2)];
            float4 q3 = s[slot_of(lane, 3)];
            __syncwarp();   // all lanes done reading stage k%3 before re-fill below
            issue_tile(y, f0 + (k + 3) * WARPS, B0, lane, stg + ((k + 3) % 3) * 128);

            float v1[4];
#define ACC_S(i, c0r, c0i, c1r, c1i)              \
            { float t00 = c0r*c0r + c0i*c0i;      \
              float t11 = c1r*c1r + c1i*c1i;      \
              a00[i] += t00;                      \
              a11[i] += t11;                      \
              are[i] += c0r*c1r + c0i*c1i;        \
              aim[i] += c0i*c1r - c0r*c1i;        \
              v1[i] = 0.5f * (t00 + t11); }
            ACC_S(0, q0.x, q1.x, q2.x, q3.x)
            ACC_S(1, q0.y, q1.y, q2.y, q3.y)
            ACC_S(2, q0.z, q1.z, q2.z, q3.z)
            ACC_S(3, q0.w, q1.w, q2.w, q3.w)
#undef ACC_S
            int f = f0 + k * WARPS;
            if (bok && f < NF)   // regular store -> stays in L2 for phase B
                vout[(size_t)f * NB + b] = make_float4(v1[0], v1[1], v1[2], v1[3]);
        }
        CP_WAIT0();
        __syncthreads();   // staging -> red overlay handoff (cross-warp)
        block_reduce_atomic(a00, a11, are, aim, b, bok, g_acc1, red);
    }
    group_barrier(bar1);   // only the NTY blocks sharing bx

    // ====== Phase B: rebuild yc1 from (v1, R1, x); accumulate R2; v2 -> vout ===
    // Loads pipelined via lane-private cp.async staging (register-free MLP).
    {
        float a00[4] = {0,0,0,0}, a11[4] = {0,0,0,0}, are[4] = {0,0,0,0}, aim[4] = {0,0,0,0};
        float4 Rn[4];
#pragma unroll
        for (int s = 0; s < 4; s++) Rn[s] = norm_acc(g_acc1[bc * 4 + s]);

        issue_vx(vout, x, f0 + (KF - 1) * WARPS, B0, lane, stg + ((KF - 1) % 3) * 64);
        issue_vx(vout, x, f0 + (KF - 2) * WARPS, B0, lane, stg + ((KF - 2) % 3) * 64);
        issue_vx(vout, x, f0 + (KF - 3) * WARPS, B0, lane, stg + ((KF - 3) % 3) * 64);
#pragma unroll
        for (int k = KF - 1; k >= 0; k--) {     // reverse: freshest v1 lines first
            CP_WAIT2();
            float4* s = stg + (k % 3) * 64;
            float4 vv = s[lane];                // lane-private: no syncwarp needed
            float4 xv = s[32 + lane];
            issue_vx(vout, x, f0 + (k - 3) * WARPS, B0, lane, s);   // same slot, dist 3

            float v[4] = {vv.x, vv.y, vv.z, vv.w};
            float c00 = SQEPS, c11 = SQEPS, cre = 0.f, cim = 0.f;
#pragma unroll
            for (int s2 = 0; s2 < 4; s2++) {
                c00 += v[s2] * Rn[s2].x;
                c11 += v[s2] * Rn[s2].y;
                cre += v[s2] * Rn[s2].z;
                cim += v[s2] * Rn[s2].w;
            }
            float det = c00 * c11 - (cre * cre + cim * cim);
            float id = 1.0f / det;
            float w0r = id * (c11 * xv.x - (cre * xv.z - cim * xv.w));
            float w0i = id * (c11 * xv.y - (cre * xv.w + cim * xv.z));
            float w1r = id * (c00 * xv.z - (cre * xv.x + cim * xv.y));
            float w1i = id * (c00 * xv.w - (cre * xv.y - cim * xv.x));

            float v2[4];
#pragma unroll
            for (int s2 = 0; s2 < 4; s2++) {
                // OOB lanes have v=0, x=0 -> all terms 0; accumulating is harmless
                float o0r = v[s2] * (Rn[s2].x * w0r + Rn[s2].z * w1r - Rn[s2].w * w1i);
                float o0i = v[s2] * (Rn[s2].x * w0i + Rn[s2].z * w1i + Rn[s2].w * w1r);
                float o1r = v[s2] * (Rn[s2].z * w0r + Rn[s2].w * w0i + Rn[s2].y * w1r);
                float o1i = v[s2] * (Rn[s2].z * w0i - Rn[s2].w * w0r + Rn[s2].y * w1i);
                float t00 = o0r*o0r + o0i*o0i;
                float t11 = o1r*o1r + o1i*o1i;
                a00[s2] += t00;
                a11[s2] += t11;
                are[s2] += o0r*o1r + o0i*o1i;
                aim[s2] += o0i*o1r - o0r*o1i;
                v2[s2] = 0.5f * (t00 + t11);
            }
            int f = f0 + k * WARPS;
            if (bok && f < NF)   // overwrite v1 with v2; stays in L2 for phase C
                vout[(size_t)f * NB + b] = make_float4(v2[0], v2[1], v2[2], v2[3]);
        }
        CP_WAIT0();       // drain zero-fill stragglers before red overlay reuse
        __syncthreads();
        block_reduce_atomic(a00, a11, are, aim, b, bok, g_acc2, red);
    }
    group_barrier(bar2);

    // ====== Phase C: iter-2 filter from (v2, x) [L2-hot], coalesced y_out ======
    {
        float4 Rn[4];
#pragma unroll
        for (int s = 0; s < 4; s++) Rn[s] = norm_acc(g_acc2[bc * 4 + s]);

        if (blockIdx.y == 0 && ty == 0 && bok) {   // emit R_out (B, C, C, 2, S)
#pragma unroll
            for (int s = 0; s < 4; s++) {
                float* p = rout + b * 32 + s;
                p[0]  = Rn[s].x;  p[4]  = 0.f;        // R[0,0]
                p[8]  = Rn[s].z;  p[12] = Rn[s].w;    // R[0,1]
                p[16] = Rn[s].z;  p[20] = -Rn[s].w;   // R[1,0] = conj
                p[24] = Rn[s].y;  p[28] = 0.f;        // R[1,1]
            }
        }

        float4* sp = stg + 192;   // transpose buffer (disjoint from vx staging 0..191)
        issue_vx(vout, x, f0 + 0 * WARPS, B0, lane, stg + 0 * 64);
        issue_vx(vout, x, f0 + 1 * WARPS, B0, lane, stg + 1 * 64);
        issue_vx(vout, x, f0 + 2 * WARPS, B0, lane, stg + 2 * 64);
#pragma unroll
        for (int k = 0; k < KF; k++) {
            int f = f0 + k * WARPS;
            bool fok = f < NF;                        // warp-uniform
            CP_WAIT2();
            float4* s = stg + (k % 3) * 64;
            float4 vv = s[lane];
            float4 xv = s[32 + lane];
            issue_vx(vout, x, f0 + (k + 3) * WARPS, B0, lane, s);

            float va[4] = {vv.x, vv.y, vv.z, vv.w};
            float c00 = SQEPS, c11 = SQEPS, cre = 0.f, cim = 0.f;
#pragma unroll
            for (int s2 = 0; s2 < 4; s2++) {
                c00 += va[s2] * Rn[s2].x;
                c11 += va[s2] * Rn[s2].y;
                cre += va[s2] * Rn[s2].z;
                cim += va[s2] * Rn[s2].w;
            }
            float det = c00 * c11 - (cre * cre + cim * cim);
            float id = 1.0f / det;
            float w0r = id * (c11 * xv.x - (cre * xv.z - cim * xv.w));
            float w0i = id * (c11 * xv.y - (cre * xv.w + cim * xv.z));
            float w1r = id * (c00 * xv.z - (cre * xv.x + cim * xv.y));
            float w1i = id * (c00 * xv.w - (cre * xv.y - cim * xv.x));

            float o0r[4], o0i[4], o1r[4], o1i[4];
#pragma unroll
            for (int s2 = 0; s2 < 4; s2++) {
                o0r[s2] = va[s2] * (Rn[s2].x * w0r + Rn[s2].z * w1r - Rn[s2].w * w1i);
                o0i[s2] = va[s2] * (Rn[s2].x * w0i + Rn[s2].z * w1i + Rn[s2].w * w1r);
                o1r[s2] = va[s2] * (Rn[s2].z * w0r + Rn[s2].w * w0i + Rn[s2].y * w1r);
                o1i[s2] = va[s2] * (Rn[s2].z * w0i - Rn[s2].w * w0r + Rn[s2].y * w1i);
            }

            if (fok) {   // warp-uniform: smem transpose -> coalesced STG
                __syncwarp();
                sp[slot_of(lane, 0)] = make_float4(o0r[0], o0r[1], o0r[2], o0r[3]);
                sp[slot_of(lane, 1)] = make_float4(o0i[0], o0i[1], o0i[2], o0i[3]);
                sp[slot_of(lane, 2)] = make_float4(o1r[0], o1r[1], o1r[2], o1r[3]);
                sp[slot_of(lane, 3)] = make_float4(o1i[0], o1i[1], o1i[2], o1i[3]);
                __syncwarp();
                float4* base = yout + ((size_t)f * NB + B0) * 4;
#pragma unroll
                for (int r = 0; r < 4; r++) {
                    int j = r * 32 + lane;
                    int bl = j >> 2, c = j & 3;
                    if (B0 + bl < NB)
                        __stcs(base + j, sp[slot_of(bl, c)]);
                }
            }
        }
        CP_WAIT0();   // drain stragglers before exit
    }

    // Reset this group's g_acc1 slice for the next replay.
    if (blockIdx.y == 0 && tid < 128) {
        g_acc1[bx * 128 + tid] = make_float4(0.f, 0.f, 0.f, 0.f);
    }

    // Last of the NTY group blocks out resets the group's barrier counters.
    if (tid == 0) {
        __threadfence();
        if (atomicAdd(fin, 1u) == (unsigned)(NTY - 1)) {
            *bar1 = 0; *bar2 = 0; *fin = 0;
            __threadfence();
        }
    }
}

extern "C" void kernel_launch(void* const* d_in, const int* in_sizes, int n_in,
                              void* d_out, int out_size)
{
    const float4* y = (const float4*)d_in[0];
    const float4* x = (const float4*)d_in[1];
    float* out = (float*)d_out;

    float4* yout = (float4*)out;                                     // (F,B,C,2,S)
    float4* vout = (float4*)(out + (size_t)NF * NB * 16);            // (F,B,S)
    float*  rout = out + (size_t)NF * NB * 16 + (size_t)NF * NB * 4; // (B,C,C,2,S)

    dim3 blk(32, WARPS);
    dim3 grd(NBX, NTY);
    k_fused<<<grd, blk>>>(y, x, vout, yout, rout);
}